// round 1
// baseline (speedup 1.0000x reference)
#include <cuda_runtime.h>
#include <cuda_bf16.h>
#include <math.h>

// Problem constants
#define BB    2048   // batch
#define DD    512    // hidden dim
#define GG    2048   // 4*D gate dim
#define TSRC  32
#define TTGT  32
#define DTGT  80
#define NL    2

// ---------------- persistent scratch (device globals; no cudaMalloc) ----------------
__device__ float g_X[2][(size_t)TSRC * BB * DD];  // ping/pong layer activation sequences
__device__ float g_gates[(size_t)BB * GG];        // per-step gate pre-activations
__device__ float g_h[NL][(size_t)BB * DD];
__device__ float g_c[NL][(size_t)BB * DD];
__device__ float g_prev[(size_t)BB * DD];         // decoder input embedding

// ---------------- dual GEMM: out[m][n] = sum_k A1[m][k]W1[n][k] + A2[m][k]W2[n][k] + b1[n]+b2[n]
// M = 2048 (batch), N = 2048 (gates), K = 512 per pass, two passes.
#define BM 128
#define BN 128
#define BK 16
#define TM 8
#define TN 8

__global__ __launch_bounds__(256, 2)
void dual_gemm_gates(const float* __restrict__ A1, const float* __restrict__ W1,
                     const float* __restrict__ A2, const float* __restrict__ W2,
                     const float* __restrict__ b1, const float* __restrict__ b2,
                     float* __restrict__ out)
{
    __shared__ float As[BK][BM];
    __shared__ float Bs[BK][BN];

    const int tid = threadIdx.x;
    const int tx  = tid & 15;        // 16 cols of threads
    const int ty  = tid >> 4;        // 16 rows of threads
    const int row0 = blockIdx.y * BM;
    const int col0 = blockIdx.x * BN;

    float acc[TM][TN];
    #pragma unroll
    for (int i = 0; i < TM; i++)
        #pragma unroll
        for (int j = 0; j < TN; j++) acc[i][j] = 0.f;

    #pragma unroll 1
    for (int pass = 0; pass < 2; ++pass) {
        const float* __restrict__ A = pass ? A2 : A1;
        const float* __restrict__ W = pass ? W2 : W1;

        #pragma unroll 1
        for (int k0 = 0; k0 < DD; k0 += BK) {
            // Load A tile (BM x BK) transposed into As[k][m]; 512 float4s by 256 threads
            #pragma unroll
            for (int i = tid; i < BM * (BK / 4); i += 256) {
                int r  = i >> 2;            // row within tile
                int c4 = i & 3;             // float4 index within row
                float4 v = *(const float4*)&A[(size_t)(row0 + r) * DD + k0 + c4 * 4];
                As[c4 * 4 + 0][r] = v.x;
                As[c4 * 4 + 1][r] = v.y;
                As[c4 * 4 + 2][r] = v.z;
                As[c4 * 4 + 3][r] = v.w;
            }
            // Load W tile (BN x BK) transposed into Bs[k][n]
            #pragma unroll
            for (int i = tid; i < BN * (BK / 4); i += 256) {
                int r  = i >> 2;
                int c4 = i & 3;
                float4 v = *(const float4*)&W[(size_t)(col0 + r) * DD + k0 + c4 * 4];
                Bs[c4 * 4 + 0][r] = v.x;
                Bs[c4 * 4 + 1][r] = v.y;
                Bs[c4 * 4 + 2][r] = v.z;
                Bs[c4 * 4 + 3][r] = v.w;
            }
            __syncthreads();

            #pragma unroll
            for (int k = 0; k < BK; k++) {
                float a[TM], b[TN];
                float4 a0 = *(const float4*)&As[k][ty * TM];
                float4 a1 = *(const float4*)&As[k][ty * TM + 4];
                a[0]=a0.x; a[1]=a0.y; a[2]=a0.z; a[3]=a0.w;
                a[4]=a1.x; a[5]=a1.y; a[6]=a1.z; a[7]=a1.w;
                float4 b0 = *(const float4*)&Bs[k][tx * TN];
                float4 b1v = *(const float4*)&Bs[k][tx * TN + 4];
                b[0]=b0.x; b[1]=b0.y; b[2]=b0.z; b[3]=b0.w;
                b[4]=b1v.x; b[5]=b1v.y; b[6]=b1v.z; b[7]=b1v.w;
                #pragma unroll
                for (int i = 0; i < TM; i++)
                    #pragma unroll
                    for (int j = 0; j < TN; j++)
                        acc[i][j] = fmaf(a[i], b[j], acc[i][j]);
            }
            __syncthreads();
        }
    }

    #pragma unroll
    for (int i = 0; i < TM; i++) {
        int m = row0 + ty * TM + i;
        #pragma unroll
        for (int j = 0; j < TN; j++) {
            int n = col0 + tx * TN + j;
            out[(size_t)m * GG + n] = acc[i][j] + b1[n] + b2[n];
        }
    }
}

// ---------------- LSTM pointwise cell ----------------
__device__ __forceinline__ float sigf(float x) { return 1.f / (1.f + expf(-x)); }

__global__ void lstm_cell_kernel(const float* __restrict__ gates,
                                 float* __restrict__ c, float* __restrict__ h,
                                 float* __restrict__ xout)
{
    int idx = blockIdx.x * blockDim.x + threadIdx.x;
    if (idx >= BB * DD) return;
    int b = idx >> 9;          // /512
    int d = idx & 511;
    const float* g = gates + (size_t)b * GG;
    float gi = sigf(g[d]);
    float gf = sigf(g[DD + d]);
    float gg = tanhf(g[2 * DD + d]);
    float go = sigf(g[3 * DD + d]);
    float cn = gf * c[idx] + gi * gg;
    float hn = go * tanhf(cn);
    c[idx] = cn;
    h[idx] = hn;
    if (xout) xout[idx] = hn;
}

// ---------------- embeddings ----------------
__global__ void embed_enc_kernel(const int* __restrict__ src,
                                 const float* __restrict__ emb,
                                 float* __restrict__ X)
{
    int g = blockIdx.x * blockDim.x + threadIdx.x;   // over TSRC*BB*128 float4s
    if (g >= TSRC * BB * (DD / 4)) return;
    int d4 = g & 127;
    int tb = g >> 7;
    int t = tb / BB;
    int b = tb % BB;
    int tok = src[b * TSRC + t];
    ((float4*)X)[(size_t)tb * 128 + d4] =
        ((const float4*)emb)[(size_t)tok * 128 + d4];
}

__global__ void embed_dec0_kernel(const int* __restrict__ tgt,
                                  const float* __restrict__ emb,
                                  float* __restrict__ prev)
{
    int g = blockIdx.x * blockDim.x + threadIdx.x;   // over BB*128 float4s
    if (g >= BB * (DD / 4)) return;
    int d4 = g & 127;
    int b = g >> 7;
    int tok = tgt[b * TTGT + 0];
    ((float4*)prev)[(size_t)b * 128 + d4] =
        ((const float4*)emb)[(size_t)tok * 128 + d4];
}

// ---------------- output projection ----------------
__global__ void logits_kernel(const float* __restrict__ h,
                              const float* __restrict__ W,
                              const float* __restrict__ bias,
                              float* __restrict__ out, int t)
{
    __shared__ float hs[DD];
    int b = blockIdx.x;
    for (int i = threadIdx.x; i < DD; i += blockDim.x)
        hs[i] = h[(size_t)b * DD + i];
    __syncthreads();
    int n = threadIdx.x;
    if (n < DTGT) {
        const float* w = W + (size_t)n * DD;
        float acc = bias[n];
        #pragma unroll 8
        for (int k = 0; k < DD; k++) acc = fmaf(hs[k], w[k], acc);
        out[(size_t)b * (TTGT * DTGT) + t * DTGT + n] = acc;
    }
}

// ---------------- greedy argmax + next-step embedding ----------------
__global__ void argmax_embed_kernel(const float* __restrict__ out, int t,
                                    const float* __restrict__ emb,
                                    float* __restrict__ prev)
{
    __shared__ float logi[DTGT];
    __shared__ int pred;
    int b = blockIdx.x;
    const float* row = out + (size_t)b * (TTGT * DTGT) + t * DTGT;
    if (threadIdx.x < DTGT) logi[threadIdx.x] = row[threadIdx.x];
    __syncthreads();
    if (threadIdx.x == 0) {
        float best = logi[0];
        int bi = 0;
        for (int i = 1; i < DTGT; i++)
            if (logi[i] > best) { best = logi[i]; bi = i; }   // strict > => first index on ties
        pred = bi;
    }
    __syncthreads();
    const float4* e = (const float4*)(emb + (size_t)pred * DD);
    float4* p = (float4*)(prev + (size_t)b * DD);
    for (int i = threadIdx.x; i < DD / 4; i += blockDim.x) p[i] = e[i];
}

// ---------------- host orchestration ----------------
extern "C" void kernel_launch(void* const* d_in, const int* in_sizes, int n_in,
                              void* d_out, int out_size)
{
    const int*   src     = (const int*)  d_in[0];
    const int*   tgt     = (const int*)  d_in[1];
    const float* enc_emb = (const float*)d_in[2];
    const float* dec_emb = (const float*)d_in[3];
    const float* enc_Wih = (const float*)d_in[4];
    const float* enc_Whh = (const float*)d_in[5];
    const float* enc_bih = (const float*)d_in[6];
    const float* enc_bhh = (const float*)d_in[7];
    const float* dec_Wih = (const float*)d_in[8];
    const float* dec_Whh = (const float*)d_in[9];
    const float* dec_bih = (const float*)d_in[10];
    const float* dec_bhh = (const float*)d_in[11];
    const float* post_W  = (const float*)d_in[12];
    const float* post_b  = (const float*)d_in[13];
    float* out = (float*)d_out;

    float *Xa, *gates, *h, *c, *prev;
    cudaGetSymbolAddress((void**)&Xa,    g_X);
    cudaGetSymbolAddress((void**)&gates, g_gates);
    cudaGetSymbolAddress((void**)&h,     g_h);
    cudaGetSymbolAddress((void**)&c,     g_c);
    cudaGetSymbolAddress((void**)&prev,  g_prev);
    float* Xb = Xa + (size_t)TSRC * BB * DD;

    cudaMemsetAsync(h, 0, (size_t)NL * BB * DD * sizeof(float), 0);
    cudaMemsetAsync(c, 0, (size_t)NL * BB * DD * sizeof(float), 0);

    const dim3 gemm_grid(GG / BN, BB / BM);   // 16 x 16
    const int  cell_blocks = (BB * DD + 255) / 256;

    // ---- encoder ----
    {
        int total = TSRC * BB * (DD / 4);
        embed_enc_kernel<<<(total + 255) / 256, 256>>>(src, enc_emb, Xa);
    }
    for (int l = 0; l < NL; l++) {
        const float* Wih = enc_Wih + (size_t)l * GG * DD;
        const float* Whh = enc_Whh + (size_t)l * GG * DD;
        const float* bih = enc_bih + (size_t)l * GG;
        const float* bhh = enc_bhh + (size_t)l * GG;
        float* Xin  = l ? Xb : Xa;
        float* Xout = l ? nullptr : Xb;     // only layer0 output sequence is consumed
        float* hl = h + (size_t)l * BB * DD;
        float* cl = c + (size_t)l * BB * DD;
        for (int t = 0; t < TSRC; t++) {
            dual_gemm_gates<<<gemm_grid, 256>>>(Xin + (size_t)t * BB * DD, Wih,
                                                hl, Whh, bih, bhh, gates);
            lstm_cell_kernel<<<cell_blocks, 256>>>(gates, cl, hl,
                Xout ? Xout + (size_t)t * BB * DD : nullptr);
        }
    }

    // ---- decoder (greedy) ----
    {
        int total = BB * (DD / 4);
        embed_dec0_kernel<<<(total + 255) / 256, 256>>>(tgt, dec_emb, prev);
    }
    for (int t = 0; t < TTGT; t++) {
        for (int l = 0; l < NL; l++) {
            const float* x  = (l == 0) ? prev : (h + 0 * (size_t)BB * DD);
            const float* Wih = dec_Wih + (size_t)l * GG * DD;
            const float* Whh = dec_Whh + (size_t)l * GG * DD;
            const float* bih = dec_bih + (size_t)l * GG;
            const float* bhh = dec_bhh + (size_t)l * GG;
            float* hl = h + (size_t)l * BB * DD;
            float* cl = c + (size_t)l * BB * DD;
            dual_gemm_gates<<<gemm_grid, 256>>>(x, Wih, hl, Whh, bih, bhh, gates);
            lstm_cell_kernel<<<cell_blocks, 256>>>(gates, cl, hl, nullptr);
        }
        logits_kernel<<<BB, 128>>>(h + (size_t)(NL - 1) * BB * DD, post_W, post_b, out, t);
        argmax_embed_kernel<<<BB, 128>>>(out, t, dec_emb, prev);
    }
}

// round 4
// speedup vs baseline: 1.4052x; 1.4052x over previous
#include <cuda_runtime.h>
#include <cuda_bf16.h>
#include <math.h>
#include <stdint.h>

// Problem constants
#define BB    2048
#define DD    512
#define GG    2048
#define TSRC  32
#define TTGT  32
#define DTGT  80
#define NL    2

// GEMM tiling
#define CTA_M 128
#define CTA_N 128
#define NSTAGE 4
#define KSTEPS 32          // 2 passes * (512/32) k32 chunks

#define STAGE_BYTES 49152
#define OFF_A0 0
#define OFF_A1 8192
#define OFF_A2 16384
#define OFF_B0 24576
#define OFF_B1 32768
#define OFF_B2 40960
#define BIAS_OFF (NSTAGE * STAGE_BYTES)          // 196608
#define SMEM_TOTAL_GEMM (BIAS_OFF + CTA_N * 4)   // 197120

#define SWZ(x) ((uint32_t)(x) ^ ((((uint32_t)(x)) >> 3) & 0x70))

// ---------------- persistent scratch (3 bf16 planes per tensor) ----------------
__device__ __align__(256) __nv_bfloat16 g_X0[2][(size_t)TSRC * BB * DD];
__device__ __align__(256) __nv_bfloat16 g_X1[2][(size_t)TSRC * BB * DD];
__device__ __align__(256) __nv_bfloat16 g_X2[2][(size_t)TSRC * BB * DD];
__device__ __align__(256) __nv_bfloat16 g_W0[8][(size_t)GG * DD];
__device__ __align__(256) __nv_bfloat16 g_W1[8][(size_t)GG * DD];
__device__ __align__(256) __nv_bfloat16 g_W2[8][(size_t)GG * DD];
__device__ __align__(256) __nv_bfloat16 g_h0[NL][(size_t)BB * DD];
__device__ __align__(256) __nv_bfloat16 g_h1[NL][(size_t)BB * DD];
__device__ __align__(256) __nv_bfloat16 g_h2[NL][(size_t)BB * DD];
__device__ __align__(256) __nv_bfloat16 g_p0[(size_t)BB * DD];
__device__ __align__(256) __nv_bfloat16 g_p1[(size_t)BB * DD];
__device__ __align__(256) __nv_bfloat16 g_p2[(size_t)BB * DD];
__device__ float g_gates[(size_t)BB * GG];
__device__ float g_h[NL][(size_t)BB * DD];
__device__ float g_c[NL][(size_t)BB * DD];

// ---------------- PTX helpers ----------------
__device__ __forceinline__ uint32_t smem_u32(const void* p) {
    uint32_t a;
    asm("{ .reg .u64 t; cvta.to.shared.u64 t, %1; cvt.u32.u64 %0, t; }" : "=r"(a) : "l"(p));
    return a;
}
__device__ __forceinline__ void cpasync16(uint32_t dst, const void* src) {
    asm volatile("cp.async.cg.shared.global [%0], [%1], 16;" :: "r"(dst), "l"(src));
}
#define CP_COMMIT()  asm volatile("cp.async.commit_group;" ::: "memory")
#define CP_WAIT(n)   asm volatile("cp.async.wait_group %0;" :: "n"(n) : "memory")

__device__ __forceinline__ void ldsm4(uint32_t* d, uint32_t addr) {
    asm volatile("ldmatrix.sync.aligned.m8n8.x4.shared.b16 {%0,%1,%2,%3}, [%4];"
        : "=r"(d[0]), "=r"(d[1]), "=r"(d[2]), "=r"(d[3]) : "r"(addr));
}
__device__ __forceinline__ void mma16816(float* c, const uint32_t* a, const uint32_t* b) {
    asm volatile(
        "mma.sync.aligned.m16n8k16.row.col.f32.bf16.bf16.f32 "
        "{%0,%1,%2,%3},{%4,%5,%6,%7},{%8,%9},{%0,%1,%2,%3};"
        : "+f"(c[0]), "+f"(c[1]), "+f"(c[2]), "+f"(c[3])
        : "r"(a[0]), "r"(a[1]), "r"(a[2]), "r"(a[3]), "r"(b[0]), "r"(b[1]));
}

// ---- GEMM: out = A1@W1^T + A2@W2^T + b1 + b2, 3-way bf16 split, 6 products ----
__global__ __launch_bounds__(256, 1)
void gates_mma(const __nv_bfloat16* __restrict__ A1p0, const __nv_bfloat16* __restrict__ A1p1,
               const __nv_bfloat16* __restrict__ A1p2,
               const __nv_bfloat16* __restrict__ W1p0, const __nv_bfloat16* __restrict__ W1p1,
               const __nv_bfloat16* __restrict__ W1p2,
               const __nv_bfloat16* __restrict__ A2p0, const __nv_bfloat16* __restrict__ A2p1,
               const __nv_bfloat16* __restrict__ A2p2,
               const __nv_bfloat16* __restrict__ W2p0, const __nv_bfloat16* __restrict__ W2p1,
               const __nv_bfloat16* __restrict__ W2p2,
               const float* __restrict__ b1, const float* __restrict__ b2,
               float* __restrict__ out)
{
    extern __shared__ char smem[];
    const uint32_t sb = smem_u32(smem);
    const int tid  = threadIdx.x;
    const int wid  = tid >> 5;
    const int lane = tid & 31;
    const int row0 = blockIdx.y * CTA_M;
    const int col0 = blockIdx.x * CTA_N;
    const int warp_m = (wid & 3) * 32;
    const int warp_n = (wid >> 2) * 64;

    if (tid < CTA_N)
        ((float*)(smem + BIAS_OFF))[tid] = b1[col0 + tid] + b2[col0 + tid];

    // stage loader: s in [0,KSTEPS); slot in [0,NSTAGE)
    auto load_stage = [&](int s, int slot) {
        const int pass = s >> 4;
        const size_t k0b = (size_t)(s & 15) * 64;     // 32 elems * 2B
        const char* srcs[6];
        srcs[0] = (const char*)(pass ? A2p0 : A1p0) + (size_t)row0 * (DD * 2) + k0b;
        srcs[1] = (const char*)(pass ? A2p1 : A1p1) + (size_t)row0 * (DD * 2) + k0b;
        srcs[2] = (const char*)(pass ? A2p2 : A1p2) + (size_t)row0 * (DD * 2) + k0b;
        srcs[3] = (const char*)(pass ? W2p0 : W1p0) + (size_t)col0 * (DD * 2) + k0b;
        srcs[4] = (const char*)(pass ? W2p1 : W1p1) + (size_t)col0 * (DD * 2) + k0b;
        srcs[5] = (const char*)(pass ? W2p2 : W1p2) + (size_t)col0 * (DD * 2) + k0b;
        const uint32_t base = sb + slot * STAGE_BYTES;
        #pragma unroll
        for (int tile = 0; tile < 6; tile++) {
            #pragma unroll
            for (int hh = 0; hh < 2; hh++) {
                int j = hh * 256 + tid;          // 0..511
                int r = j >> 2, u = j & 3;
                cpasync16(base + tile * 8192 + SWZ(r * 64 + u * 16),
                          srcs[tile] + (size_t)r * (DD * 2) + u * 16);
            }
        }
        CP_COMMIT();
    };

    float acc[2][8][4];
    #pragma unroll
    for (int i = 0; i < 2; i++)
        #pragma unroll
        for (int j = 0; j < 8; j++)
            #pragma unroll
            for (int k = 0; k < 4; k++) acc[i][j][k] = 0.f;

    load_stage(0, 0);
    load_stage(1, 1);
    load_stage(2, 2);

    // lane-derived ldmatrix address components
    const int laA = lane & 15;                          // A row within m16
    const int luA = lane >> 4;                          // A k-16B-unit
    const int laB = (lane & 7) + ((lane >> 4) << 3);    // B row within n16
    const int luB = (lane >> 3) & 1;                    // B k-16B-unit

    #pragma unroll 1
    for (int s = 0; s < KSTEPS; s++) {
        if (s + 3 < KSTEPS) load_stage(s + 3, (s + 3) & 3);
        else CP_COMMIT();
        CP_WAIT(3);
        __syncthreads();

        const uint32_t stg = sb + (s & 3) * STAGE_BYTES;
        #pragma unroll
        for (int kh = 0; kh < 2; kh++) {         // two k16 steps per k32 stage
            uint32_t A[3][2][4];
            #pragma unroll
            for (int am = 0; am < 2; am++) {
                uint32_t off = SWZ((warp_m + am * 16 + laA) * 64 + kh * 32 + luA * 16);
                ldsm4(A[0][am], stg + OFF_A0 + off);
                ldsm4(A[1][am], stg + OFF_A1 + off);
                ldsm4(A[2][am], stg + OFF_A2 + off);
            }
            #pragma unroll
            for (int g = 0; g < 4; g++) {
                uint32_t Bf[3][4];
                uint32_t offb = SWZ((warp_n + g * 16 + laB) * 64 + kh * 32 + luB * 16);
                ldsm4(Bf[0], stg + OFF_B0 + offb);
                ldsm4(Bf[1], stg + OFF_B1 + offb);
                ldsm4(Bf[2], stg + OFF_B2 + offb);
                #pragma unroll
                for (int am = 0; am < 2; am++)
                    #pragma unroll
                    for (int sub = 0; sub < 2; sub++) {
                        float* c = acc[am][g * 2 + sub];
                        mma16816(c, A[0][am], &Bf[0][sub * 2]);
                        mma16816(c, A[0][am], &Bf[1][sub * 2]);
                        mma16816(c, A[1][am], &Bf[0][sub * 2]);
                        mma16816(c, A[0][am], &Bf[2][sub * 2]);
                        mma16816(c, A[1][am], &Bf[1][sub * 2]);
                        mma16816(c, A[2][am], &Bf[0][sub * 2]);
                    }
            }
        }
        __syncthreads();
    }

    // epilogue: bias + float2 stores
    const float* bias_s = (const float*)(smem + BIAS_OFF);
    #pragma unroll
    for (int am = 0; am < 2; am++)
        #pragma unroll
        for (int g = 0; g < 4; g++)
            #pragma unroll
            for (int sub = 0; sub < 2; sub++) {
                int nb = warp_n + g * 16 + sub * 8 + (lane & 3) * 2;
                int mb = row0 + warp_m + am * 16 + (lane >> 2);
                float bv0 = bias_s[nb], bv1 = bias_s[nb + 1];
                float* c = acc[am][g * 2 + sub];
                float2 v0 = { c[0] + bv0, c[1] + bv1 };
                float2 v1 = { c[2] + bv0, c[3] + bv1 };
                *(float2*)&out[(size_t)mb * GG + col0 + nb] = v0;
                *(float2*)&out[(size_t)(mb + 8) * GG + col0 + nb] = v1;
            }
}

// ---------------- split helpers ----------------
__device__ __forceinline__ void split3(float x, __nv_bfloat16& a0, __nv_bfloat16& a1,
                                       __nv_bfloat16& a2) {
    a0 = __float2bfloat16(x);
    float r = x - __bfloat162float(a0);
    a1 = __float2bfloat16(r);
    r -= __bfloat162float(a1);
    a2 = __float2bfloat16(r);
}

__global__ void split_kernel(const float* __restrict__ src,
                             __nv_bfloat16* __restrict__ p0, __nv_bfloat16* __restrict__ p1,
                             __nv_bfloat16* __restrict__ p2, int n)
{
    int i = blockIdx.x * 256 + threadIdx.x;
    if (i >= n) return;
    __nv_bfloat16 a0, a1, a2;
    split3(src[i], a0, a1, a2);
    p0[i] = a0; p1[i] = a1; p2[i] = a2;
}

// ---------------- LSTM pointwise cell ----------------
__device__ __forceinline__ float sigf(float x) { return 1.f / (1.f + expf(-x)); }

__global__ void lstm_cell_kernel(const float* __restrict__ gates,
                                 float* __restrict__ c, float* __restrict__ h,
                                 __nv_bfloat16* __restrict__ h0, __nv_bfloat16* __restrict__ h1,
                                 __nv_bfloat16* __restrict__ h2,
                                 __nv_bfloat16* __restrict__ x0, __nv_bfloat16* __restrict__ x1,
                                 __nv_bfloat16* __restrict__ x2)
{
    int idx = blockIdx.x * blockDim.x + threadIdx.x;
    if (idx >= BB * DD) return;
    int b = idx >> 9;
    int d = idx & 511;
    const float* g = gates + (size_t)b * GG;
    float gi = sigf(g[d]);
    float gf = sigf(g[DD + d]);
    float gg = tanhf(g[2 * DD + d]);
    float go = sigf(g[3 * DD + d]);
    float cn = gf * c[idx] + gi * gg;
    float hn = go * tanhf(cn);
    c[idx] = cn;
    h[idx] = hn;
    __nv_bfloat16 a0, a1, a2;
    split3(hn, a0, a1, a2);
    h0[idx] = a0; h1[idx] = a1; h2[idx] = a2;
    if (x0) { x0[idx] = a0; x1[idx] = a1; x2[idx] = a2; }
}

// ---------------- embeddings ----------------
__global__ void embed_enc_kernel(const int* __restrict__ src,
                                 const float* __restrict__ emb,
                                 __nv_bfloat16* __restrict__ X0, __nv_bfloat16* __restrict__ X1,
                                 __nv_bfloat16* __restrict__ X2)
{
    int g = blockIdx.x * blockDim.x + threadIdx.x;
    if (g >= TSRC * BB * (DD / 4)) return;
    int d4 = g & 127;
    int tb = g >> 7;
    int t = tb / BB;
    int b = tb % BB;
    int tok = src[b * TSRC + t];
    float4 v = ((const float4*)emb)[(size_t)tok * 128 + d4];
    size_t e = (size_t)tb * DD + d4 * 4;
    __nv_bfloat16 a0, a1, a2;
    split3(v.x, a0, a1, a2); X0[e]   = a0; X1[e]   = a1; X2[e]   = a2;
    split3(v.y, a0, a1, a2); X0[e+1] = a0; X1[e+1] = a1; X2[e+1] = a2;
    split3(v.z, a0, a1, a2); X0[e+2] = a0; X1[e+2] = a1; X2[e+2] = a2;
    split3(v.w, a0, a1, a2); X0[e+3] = a0; X1[e+3] = a1; X2[e+3] = a2;
}

__global__ void embed_dec0_kernel(const int* __restrict__ tgt,
                                  const float* __restrict__ emb,
                                  __nv_bfloat16* __restrict__ p0, __nv_bfloat16* __restrict__ p1,
                                  __nv_bfloat16* __restrict__ p2)
{
    int g = blockIdx.x * blockDim.x + threadIdx.x;
    if (g >= BB * (DD / 4)) return;
    int d4 = g & 127;
    int b = g >> 7;
    int tok = tgt[b * TTGT + 0];
    float4 v = ((const float4*)emb)[(size_t)tok * 128 + d4];
    size_t e = (size_t)b * DD + d4 * 4;
    __nv_bfloat16 a0, a1, a2;
    split3(v.x, a0, a1, a2); p0[e]   = a0; p1[e]   = a1; p2[e]   = a2;
    split3(v.y, a0, a1, a2); p0[e+1] = a0; p1[e+1] = a1; p2[e+1] = a2;
    split3(v.z, a0, a1, a2); p0[e+2] = a0; p1[e+2] = a1; p2[e+2] = a2;
    split3(v.w, a0, a1, a2); p0[e+3] = a0; p1[e+3] = a1; p2[e+3] = a2;
}

// ---------------- output projection ----------------
__global__ void logits_kernel(const float* __restrict__ h,
                              const float* __restrict__ W,
                              const float* __restrict__ bias,
                              float* __restrict__ out, int t)
{
    __shared__ float hs[DD];
    int b = blockIdx.x;
    for (int i = threadIdx.x; i < DD; i += blockDim.x)
        hs[i] = h[(size_t)b * DD + i];
    __syncthreads();
    int n = threadIdx.x;
    if (n < DTGT) {
        const float* w = W + (size_t)n * DD;
        float acc = bias[n];
        #pragma unroll 8
        for (int k = 0; k < DD; k++) acc = fmaf(hs[k], w[k], acc);
        out[(size_t)b * (TTGT * DTGT) + t * DTGT + n] = acc;
    }
}

// ---------------- greedy argmax + next embedding (emits 3 planes) ----------------
__global__ void argmax_embed_kernel(const float* __restrict__ out, int t,
                                    const float* __restrict__ emb,
                                    __nv_bfloat16* __restrict__ p0, __nv_bfloat16* __restrict__ p1,
                                    __nv_bfloat16* __restrict__ p2)
{
    __shared__ float logi[DTGT];
    __shared__ int pred;
    int b = blockIdx.x;
    const float* row = out + (size_t)b * (TTGT * DTGT) + t * DTGT;
    if (threadIdx.x < DTGT) logi[threadIdx.x] = row[threadIdx.x];
    __syncthreads();
    if (threadIdx.x == 0) {
        float best = logi[0];
        int bi = 0;
        for (int i = 1; i < DTGT; i++)
            if (logi[i] > best) { best = logi[i]; bi = i; }
        pred = bi;
    }
    __syncthreads();
    const float4* e4 = (const float4*)(emb + (size_t)pred * DD);
    for (int i = threadIdx.x; i < DD / 4; i += blockDim.x) {
        float4 v = e4[i];
        size_t e = (size_t)b * DD + i * 4;
        __nv_bfloat16 a0, a1, a2;
        split3(v.x, a0, a1, a2); p0[e]   = a0; p1[e]   = a1; p2[e]   = a2;
        split3(v.y, a0, a1, a2); p0[e+1] = a0; p1[e+1] = a1; p2[e+1] = a2;
        split3(v.z, a0, a1, a2); p0[e+2] = a0; p1[e+2] = a1; p2[e+2] = a2;
        split3(v.w, a0, a1, a2); p0[e+3] = a0; p1[e+3] = a1; p2[e+3] = a2;
    }
}

// ---------------- host orchestration ----------------
extern "C" void kernel_launch(void* const* d_in, const int* in_sizes, int n_in,
                              void* d_out, int out_size)
{
    const int*   src     = (const int*)  d_in[0];
    const int*   tgt     = (const int*)  d_in[1];
    const float* enc_emb = (const float*)d_in[2];
    const float* dec_emb = (const float*)d_in[3];
    const float* enc_Wih = (const float*)d_in[4];
    const float* enc_Whh = (const float*)d_in[5];
    const float* enc_bih = (const float*)d_in[6];
    const float* enc_bhh = (const float*)d_in[7];
    const float* dec_Wih = (const float*)d_in[8];
    const float* dec_Whh = (const float*)d_in[9];
    const float* dec_bih = (const float*)d_in[10];
    const float* dec_bhh = (const float*)d_in[11];
    const float* post_W  = (const float*)d_in[12];
    const float* post_b  = (const float*)d_in[13];
    float* out = (float*)d_out;

    cudaFuncSetAttribute(gates_mma, cudaFuncAttributeMaxDynamicSharedMemorySize, SMEM_TOTAL_GEMM);

    __nv_bfloat16 *X0, *X1, *X2, *W0, *W1, *W2, *h0, *h1, *h2, *p0, *p1, *p2;
    float *gates, *h, *c;
    cudaGetSymbolAddress((void**)&X0, g_X0);
    cudaGetSymbolAddress((void**)&X1, g_X1);
    cudaGetSymbolAddress((void**)&X2, g_X2);
    cudaGetSymbolAddress((void**)&W0, g_W0);
    cudaGetSymbolAddress((void**)&W1, g_W1);
    cudaGetSymbolAddress((void**)&W2, g_W2);
    cudaGetSymbolAddress((void**)&h0, g_h0);
    cudaGetSymbolAddress((void**)&h1, g_h1);
    cudaGetSymbolAddress((void**)&h2, g_h2);
    cudaGetSymbolAddress((void**)&p0, g_p0);
    cudaGetSymbolAddress((void**)&p1, g_p1);
    cudaGetSymbolAddress((void**)&p2, g_p2);
    cudaGetSymbolAddress((void**)&gates, g_gates);
    cudaGetSymbolAddress((void**)&h, g_h);
    cudaGetSymbolAddress((void**)&c, g_c);

    const size_t XBUF = (size_t)TSRC * BB * DD;
    const size_t WSL  = (size_t)GG * DD;
    const size_t HB   = (size_t)BB * DD;

    cudaMemsetAsync(h, 0, (size_t)NL * HB * sizeof(float), 0);
    cudaMemsetAsync(c, 0, (size_t)NL * HB * sizeof(float), 0);
    cudaMemsetAsync(h0, 0, (size_t)NL * HB * sizeof(__nv_bfloat16), 0);
    cudaMemsetAsync(h1, 0, (size_t)NL * HB * sizeof(__nv_bfloat16), 0);
    cudaMemsetAsync(h2, 0, (size_t)NL * HB * sizeof(__nv_bfloat16), 0);

    // weight splits: slots [encWih l0,l1 | encWhh l0,l1 | decWih l0,l1 | decWhh l0,l1]
    {
        int n = (int)(NL * WSL);
        int gsz = (n + 255) / 256;
        split_kernel<<<gsz, 256>>>(enc_Wih, W0 + 0 * WSL, W1 + 0 * WSL, W2 + 0 * WSL, n);
        split_kernel<<<gsz, 256>>>(enc_Whh, W0 + 2 * WSL, W1 + 2 * WSL, W2 + 2 * WSL, n);
        split_kernel<<<gsz, 256>>>(dec_Wih, W0 + 4 * WSL, W1 + 4 * WSL, W2 + 4 * WSL, n);
        split_kernel<<<gsz, 256>>>(dec_Whh, W0 + 6 * WSL, W1 + 6 * WSL, W2 + 6 * WSL, n);
    }

    const dim3 gemm_grid(GG / CTA_N, BB / CTA_M);   // 16 x 16
    const int  cell_blocks = (BB * DD + 255) / 256;

    // ---- encoder ----
    {
        int total = TSRC * BB * (DD / 4);
        embed_enc_kernel<<<(total + 255) / 256, 256>>>(src, enc_emb, X0, X1, X2);
    }
    for (int l = 0; l < NL; l++) {
        const __nv_bfloat16* Wih0 = W0 + (0 + l) * WSL;
        const __nv_bfloat16* Wih1 = W1 + (0 + l) * WSL;
        const __nv_bfloat16* Wih2 = W2 + (0 + l) * WSL;
        const __nv_bfloat16* Whh0 = W0 + (2 + l) * WSL;
        const __nv_bfloat16* Whh1 = W1 + (2 + l) * WSL;
        const __nv_bfloat16* Whh2 = W2 + (2 + l) * WSL;
        const float* bih = enc_bih + (size_t)l * GG;
        const float* bhh = enc_bhh + (size_t)l * GG;
        const __nv_bfloat16* Xi0 = X0 + (l ? XBUF : 0);
        const __nv_bfloat16* Xi1 = X1 + (l ? XBUF : 0);
        const __nv_bfloat16* Xi2 = X2 + (l ? XBUF : 0);
        __nv_bfloat16* Xo0 = l ? nullptr : X0 + XBUF;
        __nv_bfloat16* Xo1 = l ? nullptr : X1 + XBUF;
        __nv_bfloat16* Xo2 = l ? nullptr : X2 + XBUF;
        float* hl2 = h + (size_t)l * HB;
        float* cl2 = c + (size_t)l * HB;
        __nv_bfloat16* hl0 = h0 + (size_t)l * HB;
        __nv_bfloat16* hl1 = h1 + (size_t)l * HB;
        __nv_bfloat16* hl3 = h2 + (size_t)l * HB;
        for (int t = 0; t < TSRC; t++) {
            gates_mma<<<gemm_grid, 256, SMEM_TOTAL_GEMM>>>(
                Xi0 + (size_t)t * HB, Xi1 + (size_t)t * HB, Xi2 + (size_t)t * HB,
                Wih0, Wih1, Wih2,
                hl0, hl1, hl3, Whh0, Whh1, Whh2, bih, bhh, gates);
            lstm_cell_kernel<<<cell_blocks, 256>>>(gates, cl2, hl2, hl0, hl1, hl3,
                Xo0 ? Xo0 + (size_t)t * HB : nullptr,
                Xo1 ? Xo1 + (size_t)t * HB : nullptr,
                Xo2 ? Xo2 + (size_t)t * HB : nullptr);
        }
    }

    // ---- decoder ----
    {
        int total = BB * (DD / 4);
        embed_dec0_kernel<<<(total + 255) / 256, 256>>>(tgt, dec_emb, p0, p1, p2);
    }
    for (int t = 0; t < TTGT; t++) {
        for (int l = 0; l < NL; l++) {
            const __nv_bfloat16* A0 = (l == 0) ? p0 : h0;   // layer0 h for l==1
            const __nv_bfloat16* A1 = (l == 0) ? p1 : h1;
            const __nv_bfloat16* A2 = (l == 0) ? p2 : h2;
            const __nv_bfloat16* Wih0 = W0 + (4 + l) * WSL;
            const __nv_bfloat16* Wih1 = W1 + (4 + l) * WSL;
            const __nv_bfloat16* Wih2 = W2 + (4 + l) * WSL;
            const __nv_bfloat16* Whh0 = W0 + (6 + l) * WSL;
            const __nv_bfloat16* Whh1 = W1 + (6 + l) * WSL;
            const __nv_bfloat16* Whh2 = W2 + (6 + l) * WSL;
            const float* bih = dec_bih + (size_t)l * GG;
            const float* bhh = dec_bhh + (size_t)l * GG;
            float* hl2 = h + (size_t)l * HB;
            float* cl2 = c + (size_t)l * HB;
            __nv_bfloat16* hl0 = h0 + (size_t)l * HB;
            __nv_bfloat16* hl1 = h1 + (size_t)l * HB;
            __nv_bfloat16* hl3 = h2 + (size_t)l * HB;
            gates_mma<<<gemm_grid, 256, SMEM_TOTAL_GEMM>>>(
                A0, A1, A2, Wih0, Wih1, Wih2,
                hl0, hl1, hl3, Whh0, Whh1, Whh2, bih, bhh, gates);
            lstm_cell_kernel<<<cell_blocks, 256>>>(gates, cl2, hl2, hl0, hl1, hl3,
                                                   nullptr, nullptr, nullptr);
        }
        logits_kernel<<<BB, 128>>>(h + (size_t)(NL - 1) * HB, post_W, post_b, out, t);
        argmax_embed_kernel<<<BB, 128>>>(out, t, dec_emb, p0, p1, p2);
    }
}

// round 5
// speedup vs baseline: 1.5630x; 1.1123x over previous
#include <cuda_runtime.h>
#include <cuda_bf16.h>
#include <math.h>
#include <stdint.h>

// Problem constants
#define BB    2048
#define DD    512
#define GG    2048
#define TSRC  32
#define TTGT  32
#define DTGT  80
#define DSRC  100
#define NL    2

// GEMM tiling
#define CTA_M 128
#define CTA_N 128
#define NSTAGE 4

#define STAGE_BYTES 49152
#define OFF_A0 0
#define OFF_A1 8192
#define OFF_A2 16384
#define OFF_B0 24576
#define OFF_B1 32768
#define OFF_B2 40960
#define BIAS_OFF (NSTAGE * STAGE_BYTES)          // 196608
#define SMEM_TOTAL_GEMM (BIAS_OFF + CTA_N * 4)   // 197120

#define SWZ(x) ((uint32_t)(x) ^ ((((uint32_t)(x)) >> 3) & 0x70))

typedef __nv_bfloat16 bf16;

// ---------------- persistent scratch ----------------
// layer-0 output sequence planes (input to enc l1)
__device__ __align__(256) bf16 g_Xs0[(size_t)TSRC * BB * DD];
__device__ __align__(256) bf16 g_Xs1[(size_t)TSRC * BB * DD];
__device__ __align__(256) bf16 g_Xs2[(size_t)TSRC * BB * DD];
// permuted+split weights: [0]=encWhh0 [1]=encWih1 [2]=encWhh1 [3]=decWhh0 [4]=decWih1 [5]=decWhh1
__device__ __align__(256) bf16 g_Wp0[6][(size_t)GG * DD];
__device__ __align__(256) bf16 g_Wp1[6][(size_t)GG * DD];
__device__ __align__(256) bf16 g_Wp2[6][(size_t)GG * DD];
// h state planes, ping-pong per layer
__device__ __align__(256) bf16 g_hp0[NL][2][(size_t)BB * DD];
__device__ __align__(256) bf16 g_hp1[NL][2][(size_t)BB * DD];
__device__ __align__(256) bf16 g_hp2[NL][2][(size_t)BB * DD];
__device__ float g_c[NL][(size_t)BB * DD];
__device__ float g_hf[(size_t)BB * DD];        // fp32 h of layer1 (for logits)
__device__ float g_encT[(size_t)DSRC * GG];    // exact fp32 x@Wih+bih+bhh tables (permuted cols)
__device__ float g_decT[(size_t)DTGT * GG];
__device__ float g_biasE[GG];                  // permuted bih+bhh for enc l1
__device__ float g_biasD[GG];                  // permuted bih+bhh for dec l1
__device__ int   g_pred[BB];

// ---------------- PTX helpers ----------------
__device__ __forceinline__ uint32_t smem_u32(const void* p) {
    uint32_t a;
    asm("{ .reg .u64 t; cvta.to.shared.u64 t, %1; cvt.u32.u64 %0, t; }" : "=r"(a) : "l"(p));
    return a;
}
__device__ __forceinline__ void cpasync16(uint32_t dst, const void* src) {
    asm volatile("cp.async.cg.shared.global [%0], [%1], 16;" :: "r"(dst), "l"(src));
}
#define CP_COMMIT()  asm volatile("cp.async.commit_group;" ::: "memory")
#define CP_WAIT(n)   asm volatile("cp.async.wait_group %0;" :: "n"(n) : "memory")

__device__ __forceinline__ void ldsm4(uint32_t* d, uint32_t addr) {
    asm volatile("ldmatrix.sync.aligned.m8n8.x4.shared.b16 {%0,%1,%2,%3}, [%4];"
        : "=r"(d[0]), "=r"(d[1]), "=r"(d[2]), "=r"(d[3]) : "r"(addr));
}
__device__ __forceinline__ void mma16816(float* c, const uint32_t* a, const uint32_t* b) {
    asm volatile(
        "mma.sync.aligned.m16n8k16.row.col.f32.bf16.bf16.f32 "
        "{%0,%1,%2,%3},{%4,%5,%6,%7},{%8,%9},{%0,%1,%2,%3};"
        : "+f"(c[0]), "+f"(c[1]), "+f"(c[2]), "+f"(c[3])
        : "r"(a[0]), "r"(a[1]), "r"(a[2]), "r"(a[3]), "r"(b[0]), "r"(b[1]));
}

__device__ __forceinline__ void split3(float x, bf16& a0, bf16& a1, bf16& a2) {
    a0 = __float2bfloat16(x);
    float r = x - __bfloat162float(a0);
    a1 = __float2bfloat16(r);
    r -= __bfloat162float(a1);
    a2 = __float2bfloat16(r);
}
__device__ __forceinline__ float sigf(float x) { return 1.f / (1.f + expf(-x)); }

// ---- fused GEMM + LSTM cell ----
// Output column permutation: c = (d>>2)*16 + (d&3)*2 + (gate>>1)*8 + (gate&1)
// so each thread's (sub0, sub1) fragment column-pairs are (i,f) and (g,o) of one d.
template<int NPASS, bool USE_TABLE>
__global__ __launch_bounds__(256, 1)
void gemm_cell(const bf16* __restrict__ A1p0, const bf16* __restrict__ A1p1,
               const bf16* __restrict__ A1p2,
               const bf16* __restrict__ W1p0, const bf16* __restrict__ W1p1,
               const bf16* __restrict__ W1p2,
               const bf16* __restrict__ A2p0, const bf16* __restrict__ A2p1,
               const bf16* __restrict__ A2p2,
               const bf16* __restrict__ W2p0, const bf16* __restrict__ W2p1,
               const bf16* __restrict__ W2p2,
               const float* __restrict__ tableOrBias,
               const int* __restrict__ tok, int tok_stride, int tok_off,
               float* __restrict__ c_state, float* __restrict__ h_fp32,
               bf16* __restrict__ h0o, bf16* __restrict__ h1o, bf16* __restrict__ h2o,
               bf16* __restrict__ x0o, bf16* __restrict__ x1o, bf16* __restrict__ x2o)
{
    extern __shared__ char smem[];
    const uint32_t sb = smem_u32(smem);
    const int tid  = threadIdx.x;
    const int wid  = tid >> 5;
    const int lane = tid & 31;
    const int row0 = blockIdx.y * CTA_M;
    const int col0 = blockIdx.x * CTA_N;
    const int warp_m = (wid & 3) * 32;
    const int warp_n = (wid >> 2) * 64;
    const int KSTEPS = NPASS * 16;

    if (!USE_TABLE && tid < CTA_N)
        ((float*)(smem + BIAS_OFF))[tid] = tableOrBias[col0 + tid];

    auto load_stage = [&](int s, int slot) {
        const int pass = (NPASS == 2) ? (s >> 4) : 0;
        const size_t k0b = (size_t)(s & 15) * 64;
        const char* srcs[6];
        srcs[0] = (const char*)(pass ? A2p0 : A1p0) + (size_t)row0 * (DD * 2) + k0b;
        srcs[1] = (const char*)(pass ? A2p1 : A1p1) + (size_t)row0 * (DD * 2) + k0b;
        srcs[2] = (const char*)(pass ? A2p2 : A1p2) + (size_t)row0 * (DD * 2) + k0b;
        srcs[3] = (const char*)(pass ? W2p0 : W1p0) + (size_t)col0 * (DD * 2) + k0b;
        srcs[4] = (const char*)(pass ? W2p1 : W1p1) + (size_t)col0 * (DD * 2) + k0b;
        srcs[5] = (const char*)(pass ? W2p2 : W1p2) + (size_t)col0 * (DD * 2) + k0b;
        const uint32_t base = sb + slot * STAGE_BYTES;
        #pragma unroll
        for (int tile = 0; tile < 6; tile++) {
            #pragma unroll
            for (int hh = 0; hh < 2; hh++) {
                int j = hh * 256 + tid;
                int r = j >> 2, u = j & 3;
                cpasync16(base + tile * 8192 + SWZ(r * 64 + u * 16),
                          srcs[tile] + (size_t)r * (DD * 2) + u * 16);
            }
        }
        CP_COMMIT();
    };

    float acc[2][8][4];
    #pragma unroll
    for (int i = 0; i < 2; i++)
        #pragma unroll
        for (int j = 0; j < 8; j++)
            #pragma unroll
            for (int k = 0; k < 4; k++) acc[i][j][k] = 0.f;

    load_stage(0, 0);
    load_stage(1, 1);
    load_stage(2, 2);

    const int laA = lane & 15;
    const int luA = lane >> 4;
    const int laB = (lane & 7) + ((lane >> 4) << 3);
    const int luB = (lane >> 3) & 1;

    #pragma unroll 1
    for (int s = 0; s < KSTEPS; s++) {
        if (s + 3 < KSTEPS) load_stage(s + 3, (s + 3) & 3);
        else CP_COMMIT();
        CP_WAIT(3);
        __syncthreads();

        const uint32_t stg = sb + (s & 3) * STAGE_BYTES;
        #pragma unroll
        for (int kh = 0; kh < 2; kh++) {
            uint32_t A[3][2][4];
            #pragma unroll
            for (int am = 0; am < 2; am++) {
                uint32_t off = SWZ((warp_m + am * 16 + laA) * 64 + kh * 32 + luA * 16);
                ldsm4(A[0][am], stg + OFF_A0 + off);
                ldsm4(A[1][am], stg + OFF_A1 + off);
                ldsm4(A[2][am], stg + OFF_A2 + off);
            }
            #pragma unroll
            for (int g = 0; g < 4; g++) {
                uint32_t Bf[3][4];
                uint32_t offb = SWZ((warp_n + g * 16 + laB) * 64 + kh * 32 + luB * 16);
                ldsm4(Bf[0], stg + OFF_B0 + offb);
                ldsm4(Bf[1], stg + OFF_B1 + offb);
                ldsm4(Bf[2], stg + OFF_B2 + offb);
                #pragma unroll
                for (int am = 0; am < 2; am++)
                    #pragma unroll
                    for (int sub = 0; sub < 2; sub++) {
                        float* c = acc[am][g * 2 + sub];
                        mma16816(c, A[0][am], &Bf[0][sub * 2]);
                        mma16816(c, A[0][am], &Bf[1][sub * 2]);
                        mma16816(c, A[1][am], &Bf[0][sub * 2]);
                        mma16816(c, A[0][am], &Bf[2][sub * 2]);
                        mma16816(c, A[1][am], &Bf[1][sub * 2]);
                        mma16816(c, A[2][am], &Bf[0][sub * 2]);
                    }
            }
        }
        __syncthreads();
    }

    // ---- fused LSTM cell epilogue ----
    const float* bias_s = (const float*)(smem + BIAS_OFF);
    const int q = lane & 3, r = lane >> 2;
    const int dbase = ((col0 + warp_n) >> 4) * 4 + q;
    #pragma unroll
    for (int am = 0; am < 2; am++) {
        #pragma unroll
        for (int half = 0; half < 2; half++) {
            const int m = row0 + warp_m + am * 16 + r + half * 8;
            const float* trow = nullptr;
            if (USE_TABLE) {
                int tv = tok[(size_t)m * tok_stride + tok_off];
                trow = tableOrBias + (size_t)tv * GG + col0 + warp_n + q * 2;
            }
            #pragma unroll
            for (int g16 = 0; g16 < 4; g16++) {
                float* aIF = acc[am][g16 * 2 + 0];
                float* aGO = acc[am][g16 * 2 + 1];
                float gi = aIF[half * 2 + 0], gf = aIF[half * 2 + 1];
                float gg = aGO[half * 2 + 0], go = aGO[half * 2 + 1];
                if (USE_TABLE) {
                    float2 t0 = *(const float2*)(trow + g16 * 16);
                    float2 t1 = *(const float2*)(trow + g16 * 16 + 8);
                    gi += t0.x; gf += t0.y; gg += t1.x; go += t1.y;
                } else {
                    int cb = warp_n + g16 * 16 + q * 2;
                    gi += bias_s[cb]; gf += bias_s[cb + 1];
                    gg += bias_s[cb + 8]; go += bias_s[cb + 9];
                }
                float I = sigf(gi), F = sigf(gf), G = tanhf(gg), O = sigf(go);
                int d = dbase + g16 * 4;
                size_t idx = (size_t)m * DD + d;
                float cn = F * c_state[idx] + I * G;
                float hn = O * tanhf(cn);
                c_state[idx] = cn;
                if (h_fp32) h_fp32[idx] = hn;
                bf16 a0, a1, a2; split3(hn, a0, a1, a2);
                h0o[idx] = a0; h1o[idx] = a1; h2o[idx] = a2;
                if (x0o) { x0o[idx] = a0; x1o[idx] = a1; x2o[idx] = a2; }
            }
        }
    }
}

// ---------------- prep kernels ----------------
// permute+split a [GG x DD] weight matrix into 3 bf16 planes with gate-interleaved rows
__global__ void permsplit_kernel(const float* __restrict__ W,
                                 bf16* __restrict__ p0, bf16* __restrict__ p1,
                                 bf16* __restrict__ p2)
{
    size_t i = (size_t)blockIdx.x * 256 + threadIdx.x;
    if (i >= (size_t)GG * DD) return;
    int n = (int)(i >> 9), k = (int)(i & 511);
    int g = n >> 9, d = n & 511;
    int c = ((d >> 2) << 4) + ((d & 3) << 1) + ((g >> 1) << 3) + (g & 1);
    bf16 a0, a1, a2;
    split3(W[i], a0, a1, a2);
    size_t o = ((size_t)c << 9) + k;
    p0[o] = a0; p1[o] = a1; p2[o] = a2;
}

__global__ void permbias_kernel(const float* __restrict__ b1, const float* __restrict__ b2,
                                float* __restrict__ bp)
{
    int n = blockIdx.x * 256 + threadIdx.x;
    if (n >= GG) return;
    int g = n >> 9, d = n & 511;
    int c = ((d >> 2) << 4) + ((d & 3) << 1) + ((g >> 1) << 3) + (g & 1);
    bp[c] = b1[n] + b2[n];
}

// exact fp32 table: table[v][c] = emb[v] . Wih_row(c) + bih + bhh, permuted cols
__global__ void table_kernel(const float* __restrict__ emb, const float* __restrict__ Wih,
                             const float* __restrict__ bih, const float* __restrict__ bhh,
                             float* __restrict__ table)
{
    __shared__ float es[DD];
    int v = blockIdx.x;
    int c = blockIdx.y * 128 + threadIdx.x;
    for (int i = threadIdx.x; i < DD; i += 128) es[i] = emb[(size_t)v * DD + i];
    __syncthreads();
    int d = ((c >> 4) << 2) + ((c >> 1) & 3);
    int g = (((c >> 3) & 1) << 1) + (c & 1);
    int n = g * 512 + d;
    const float* w = Wih + (size_t)n * DD;
    float acc = bih[n] + bhh[n];
    #pragma unroll 8
    for (int k = 0; k < DD; k++) acc = fmaf(es[k], w[k], acc);
    table[(size_t)v * GG + c] = acc;
}

// ---------------- fused logits + argmax ----------------
__global__ void logits_argmax_kernel(const float* __restrict__ h,
                                     const float* __restrict__ W,
                                     const float* __restrict__ bias,
                                     float* __restrict__ out, int t,
                                     int* __restrict__ pred)
{
    __shared__ float hs[DD];
    __shared__ float lg[DTGT];
    int b = blockIdx.x;
    for (int i = threadIdx.x; i < DD; i += blockDim.x)
        hs[i] = h[(size_t)b * DD + i];
    __syncthreads();
    int n = threadIdx.x;
    if (n < DTGT) {
        const float* w = W + (size_t)n * DD;
        float acc = bias[n];
        #pragma unroll 8
        for (int k = 0; k < DD; k++) acc = fmaf(hs[k], w[k], acc);
        lg[n] = acc;
        out[(size_t)b * (TTGT * DTGT) + t * DTGT + n] = acc;
    }
    __syncthreads();
    if (threadIdx.x == 0) {
        float best = lg[0];
        int bi = 0;
        for (int i = 1; i < DTGT; i++)
            if (lg[i] > best) { best = lg[i]; bi = i; }
        pred[b] = bi;
    }
}

// ---------------- host orchestration ----------------
extern "C" void kernel_launch(void* const* d_in, const int* in_sizes, int n_in,
                              void* d_out, int out_size)
{
    const int*   src     = (const int*)  d_in[0];
    const int*   tgt     = (const int*)  d_in[1];
    const float* enc_emb = (const float*)d_in[2];
    const float* dec_emb = (const float*)d_in[3];
    const float* enc_Wih = (const float*)d_in[4];
    const float* enc_Whh = (const float*)d_in[5];
    const float* enc_bih = (const float*)d_in[6];
    const float* enc_bhh = (const float*)d_in[7];
    const float* dec_Wih = (const float*)d_in[8];
    const float* dec_Whh = (const float*)d_in[9];
    const float* dec_bih = (const float*)d_in[10];
    const float* dec_bhh = (const float*)d_in[11];
    const float* post_W  = (const float*)d_in[12];
    const float* post_b  = (const float*)d_in[13];
    float* out = (float*)d_out;

    cudaFuncSetAttribute(gemm_cell<1, true>,  cudaFuncAttributeMaxDynamicSharedMemorySize, SMEM_TOTAL_GEMM);
    cudaFuncSetAttribute(gemm_cell<2, false>, cudaFuncAttributeMaxDynamicSharedMemorySize, SMEM_TOTAL_GEMM);

    bf16 *Xs0, *Xs1, *Xs2, *Wp0, *Wp1, *Wp2, *hp0, *hp1, *hp2;
    float *cst, *hf, *encT, *decT, *biasE, *biasD;
    int* pred;
    cudaGetSymbolAddress((void**)&Xs0, g_Xs0);
    cudaGetSymbolAddress((void**)&Xs1, g_Xs1);
    cudaGetSymbolAddress((void**)&Xs2, g_Xs2);
    cudaGetSymbolAddress((void**)&Wp0, g_Wp0);
    cudaGetSymbolAddress((void**)&Wp1, g_Wp1);
    cudaGetSymbolAddress((void**)&Wp2, g_Wp2);
    cudaGetSymbolAddress((void**)&hp0, g_hp0);
    cudaGetSymbolAddress((void**)&hp1, g_hp1);
    cudaGetSymbolAddress((void**)&hp2, g_hp2);
    cudaGetSymbolAddress((void**)&cst, g_c);
    cudaGetSymbolAddress((void**)&hf,  g_hf);
    cudaGetSymbolAddress((void**)&encT, g_encT);
    cudaGetSymbolAddress((void**)&decT, g_decT);
    cudaGetSymbolAddress((void**)&biasE, g_biasE);
    cudaGetSymbolAddress((void**)&biasD, g_biasD);
    cudaGetSymbolAddress((void**)&pred, g_pred);

    const size_t WSL = (size_t)GG * DD;
    const size_t HB  = (size_t)BB * DD;
    const size_t XT  = (size_t)BB * DD;      // per-timestep block in Xseq

    // zero states
    cudaMemsetAsync(cst, 0, (size_t)NL * HB * sizeof(float), 0);
    cudaMemsetAsync(hp0, 0, (size_t)NL * 2 * HB * sizeof(bf16), 0);
    cudaMemsetAsync(hp1, 0, (size_t)NL * 2 * HB * sizeof(bf16), 0);
    cudaMemsetAsync(hp2, 0, (size_t)NL * 2 * HB * sizeof(bf16), 0);

    // prep: permute+split weights [0]=encWhh0 [1]=encWih1 [2]=encWhh1 [3]=decWhh0 [4]=decWih1 [5]=decWhh1
    {
        int gsz = (int)((WSL + 255) / 256);
        permsplit_kernel<<<gsz, 256>>>(enc_Whh,        Wp0 + 0 * WSL, Wp1 + 0 * WSL, Wp2 + 0 * WSL);
        permsplit_kernel<<<gsz, 256>>>(enc_Wih + WSL,  Wp0 + 1 * WSL, Wp1 + 1 * WSL, Wp2 + 1 * WSL);
        permsplit_kernel<<<gsz, 256>>>(enc_Whh + WSL,  Wp0 + 2 * WSL, Wp1 + 2 * WSL, Wp2 + 2 * WSL);
        permsplit_kernel<<<gsz, 256>>>(dec_Whh,        Wp0 + 3 * WSL, Wp1 + 3 * WSL, Wp2 + 3 * WSL);
        permsplit_kernel<<<gsz, 256>>>(dec_Wih + WSL,  Wp0 + 4 * WSL, Wp1 + 4 * WSL, Wp2 + 4 * WSL);
        permsplit_kernel<<<gsz, 256>>>(dec_Whh + WSL,  Wp0 + 5 * WSL, Wp1 + 5 * WSL, Wp2 + 5 * WSL);
        permbias_kernel<<<(GG + 255) / 256, 256>>>(enc_bih + GG, enc_bhh + GG, biasE);
        permbias_kernel<<<(GG + 255) / 256, 256>>>(dec_bih + GG, dec_bhh + GG, biasD);
        table_kernel<<<dim3(DSRC, GG / 128), 128>>>(enc_emb, enc_Wih, enc_bih, enc_bhh, encT);
        table_kernel<<<dim3(DTGT, GG / 128), 128>>>(dec_emb, dec_Wih, dec_bih, dec_bhh, decT);
    }

    const dim3 gg(GG / CTA_N, BB / CTA_M);   // 16 x 16
    int p0 = 0, p1 = 0;                      // current-state parity per layer

    // ---- encoder layer 0 (h-GEMM + table gather, writes Xseq) ----
    for (int t = 0; t < TSRC; t++) {
        bf16* in0 = hp0 + (0 * 2 + p0) * HB;  bf16* ou0 = hp0 + (0 * 2 + (p0 ^ 1)) * HB;
        bf16* in1 = hp1 + (0 * 2 + p0) * HB;  bf16* ou1 = hp1 + (0 * 2 + (p0 ^ 1)) * HB;
        bf16* in2 = hp2 + (0 * 2 + p0) * HB;  bf16* ou2 = hp2 + (0 * 2 + (p0 ^ 1)) * HB;
        gemm_cell<1, true><<<gg, 256, SMEM_TOTAL_GEMM>>>(
            in0, in1, in2, Wp0 + 0 * WSL, Wp1 + 0 * WSL, Wp2 + 0 * WSL,
            nullptr, nullptr, nullptr, nullptr, nullptr, nullptr,
            encT, src, TSRC, t,
            cst + 0 * HB, nullptr, ou0, ou1, ou2,
            Xs0 + (size_t)t * XT, Xs1 + (size_t)t * XT, Xs2 + (size_t)t * XT);
        p0 ^= 1;
    }
    // ---- encoder layer 1 (dual GEMM: Xseq + h) ----
    for (int t = 0; t < TSRC; t++) {
        bf16* in0 = hp0 + (1 * 2 + p1) * HB;  bf16* ou0 = hp0 + (1 * 2 + (p1 ^ 1)) * HB;
        bf16* in1 = hp1 + (1 * 2 + p1) * HB;  bf16* ou1 = hp1 + (1 * 2 + (p1 ^ 1)) * HB;
        bf16* in2 = hp2 + (1 * 2 + p1) * HB;  bf16* ou2 = hp2 + (1 * 2 + (p1 ^ 1)) * HB;
        gemm_cell<2, false><<<gg, 256, SMEM_TOTAL_GEMM>>>(
            Xs0 + (size_t)t * XT, Xs1 + (size_t)t * XT, Xs2 + (size_t)t * XT,
            Wp0 + 1 * WSL, Wp1 + 1 * WSL, Wp2 + 1 * WSL,
            in0, in1, in2, Wp0 + 2 * WSL, Wp1 + 2 * WSL, Wp2 + 2 * WSL,
            biasE, nullptr, 0, 0,
            cst + 1 * HB, nullptr, ou0, ou1, ou2, nullptr, nullptr, nullptr);
        p1 ^= 1;
    }

    // ---- decoder ----
    for (int t = 0; t < TTGT; t++) {
        // layer 0: h-GEMM + table gather by token (tgt[:,0] at t=0, else pred)
        bf16* i00 = hp0 + (0 * 2 + p0) * HB;  bf16* o00 = hp0 + (0 * 2 + (p0 ^ 1)) * HB;
        bf16* i01 = hp1 + (0 * 2 + p0) * HB;  bf16* o01 = hp1 + (0 * 2 + (p0 ^ 1)) * HB;
        bf16* i02 = hp2 + (0 * 2 + p0) * HB;  bf16* o02 = hp2 + (0 * 2 + (p0 ^ 1)) * HB;
        const int* tk = t ? pred : tgt;
        int ts = t ? 1 : TTGT;
        gemm_cell<1, true><<<gg, 256, SMEM_TOTAL_GEMM>>>(
            i00, i01, i02, Wp0 + 3 * WSL, Wp1 + 3 * WSL, Wp2 + 3 * WSL,
            nullptr, nullptr, nullptr, nullptr, nullptr, nullptr,
            decT, tk, ts, 0,
            cst + 0 * HB, nullptr, o00, o01, o02, nullptr, nullptr, nullptr);
        p0 ^= 1;
        // layer 1: dual GEMM (x = layer0 h of this step), writes fp32 h for logits
        bf16* i10 = hp0 + (1 * 2 + p1) * HB;  bf16* o10 = hp0 + (1 * 2 + (p1 ^ 1)) * HB;
        bf16* i11 = hp1 + (1 * 2 + p1) * HB;  bf16* o11 = hp1 + (1 * 2 + (p1 ^ 1)) * HB;
        bf16* i12 = hp2 + (1 * 2 + p1) * HB;  bf16* o12 = hp2 + (1 * 2 + (p1 ^ 1)) * HB;
        gemm_cell<2, false><<<gg, 256, SMEM_TOTAL_GEMM>>>(
            o00, o01, o02, Wp0 + 4 * WSL, Wp1 + 4 * WSL, Wp2 + 4 * WSL,
            i10, i11, i12, Wp0 + 5 * WSL, Wp1 + 5 * WSL, Wp2 + 5 * WSL,
            biasD, nullptr, 0, 0,
            cst + 1 * HB, hf, o10, o11, o12, nullptr, nullptr, nullptr);
        p1 ^= 1;
        logits_argmax_kernel<<<BB, 128>>>(hf, post_W, post_b, out, t, pred);
    }
}

// round 6
// speedup vs baseline: 2.2004x; 1.4078x over previous
#include <cuda_runtime.h>
#include <cuda_fp16.h>
#include <math.h>
#include <stdint.h>

// Problem constants
#define BB    2048
#define DD    512
#define GG    2048
#define TSRC  32
#define TTGT  32
#define DTGT  80
#define DSRC  100
#define NL    2

// GEMM tiling
#define CTA_M 128
#define CTA_N 128
#define NSTAGE 3

#define STAGE_BYTES 32768
#define OFF_A0 0
#define OFF_A1 8192
#define OFF_B0 16384
#define OFF_B1 24576
#define BIAS_OFF (NSTAGE * STAGE_BYTES)          // 98304
#define SMEM_TOTAL_GEMM (BIAS_OFF + CTA_N * 4)   // 98816

#define SWZ(x) ((uint32_t)(x) ^ ((((uint32_t)(x)) >> 3) & 0x70))

typedef __half fp16;

// ---------------- persistent scratch ----------------
// layer-0 output sequence planes (input to enc l1)
__device__ __align__(256) fp16 g_Xs0[(size_t)TSRC * BB * DD];
__device__ __align__(256) fp16 g_Xs1[(size_t)TSRC * BB * DD];
// permuted+split weights: [0]=encWhh0 [1]=encWih1 [2]=encWhh1 [3]=decWhh0 [4]=decWih1 [5]=decWhh1
__device__ __align__(256) fp16 g_Wp0[6][(size_t)GG * DD];
__device__ __align__(256) fp16 g_Wp1[6][(size_t)GG * DD];
// h state planes, ping-pong per layer
__device__ __align__(256) fp16 g_hp0[NL][2][(size_t)BB * DD];
__device__ __align__(256) fp16 g_hp1[NL][2][(size_t)BB * DD];
__device__ float g_c[NL][(size_t)BB * DD];
__device__ float g_hf[(size_t)BB * DD];        // fp32 h of layer1 (for logits)
__device__ float g_encT[(size_t)DSRC * GG];    // exact fp32 x@Wih+bih+bhh tables (permuted cols)
__device__ float g_decT[(size_t)DTGT * GG];
__device__ float g_biasE[GG];                  // permuted bih+bhh for enc l1
__device__ float g_biasD[GG];                  // permuted bih+bhh for dec l1
__device__ int   g_pred[BB];

// ---------------- PTX helpers ----------------
__device__ __forceinline__ uint32_t smem_u32(const void* p) {
    uint32_t a;
    asm("{ .reg .u64 t; cvta.to.shared.u64 t, %1; cvt.u32.u64 %0, t; }" : "=r"(a) : "l"(p));
    return a;
}
__device__ __forceinline__ void cpasync16(uint32_t dst, const void* src) {
    asm volatile("cp.async.cg.shared.global [%0], [%1], 16;" :: "r"(dst), "l"(src));
}
#define CP_COMMIT()  asm volatile("cp.async.commit_group;" ::: "memory")
#define CP_WAIT(n)   asm volatile("cp.async.wait_group %0;" :: "n"(n) : "memory")

__device__ __forceinline__ void ldsm4(uint32_t* d, uint32_t addr) {
    asm volatile("ldmatrix.sync.aligned.m8n8.x4.shared.b16 {%0,%1,%2,%3}, [%4];"
        : "=r"(d[0]), "=r"(d[1]), "=r"(d[2]), "=r"(d[3]) : "r"(addr));
}
__device__ __forceinline__ void mma16816(float* c, const uint32_t* a, const uint32_t* b) {
    asm volatile(
        "mma.sync.aligned.m16n8k16.row.col.f32.f16.f16.f32 "
        "{%0,%1,%2,%3},{%4,%5,%6,%7},{%8,%9},{%0,%1,%2,%3};"
        : "+f"(c[0]), "+f"(c[1]), "+f"(c[2]), "+f"(c[3])
        : "r"(a[0]), "r"(a[1]), "r"(a[2]), "r"(a[3]), "r"(b[0]), "r"(b[1]));
}

__device__ __forceinline__ void split2(float x, fp16& a0, fp16& a1) {
    a0 = __float2half_rn(x);
    a1 = __float2half_rn(x - __half2float(a0));
}
__device__ __forceinline__ float sigf(float x) { return 1.f / (1.f + expf(-x)); }

// ---- fused GEMM + LSTM cell ----
// Output column permutation: c = (d>>2)*16 + (d&3)*2 + (gate>>1)*8 + (gate&1)
// so each thread's (sub0, sub1) fragment column-pairs are (i,f) and (g,o) of one d.
template<int NPASS, bool USE_TABLE>
__global__ __launch_bounds__(256, 2)
void gemm_cell(const fp16* __restrict__ A1p0, const fp16* __restrict__ A1p1,
               const fp16* __restrict__ W1p0, const fp16* __restrict__ W1p1,
               const fp16* __restrict__ A2p0, const fp16* __restrict__ A2p1,
               const fp16* __restrict__ W2p0, const fp16* __restrict__ W2p1,
               const float* __restrict__ tableOrBias,
               const int* __restrict__ tok, int tok_stride, int tok_off,
               float* __restrict__ c_state, float* __restrict__ h_fp32,
               fp16* __restrict__ h0o, fp16* __restrict__ h1o,
               fp16* __restrict__ x0o, fp16* __restrict__ x1o)
{
    extern __shared__ char smem[];
    const uint32_t sb = smem_u32(smem);
    const int tid  = threadIdx.x;
    const int wid  = tid >> 5;
    const int lane = tid & 31;
    const int row0 = blockIdx.y * CTA_M;
    const int col0 = blockIdx.x * CTA_N;
    const int warp_m = (wid & 3) * 32;
    const int warp_n = (wid >> 2) * 64;
    const int KSTEPS = NPASS * 16;

    if (!USE_TABLE && tid < CTA_N)
        ((float*)(smem + BIAS_OFF))[tid] = tableOrBias[col0 + tid];

    auto load_stage = [&](int s, int slot) {
        const int pass = (NPASS == 2) ? (s >> 4) : 0;
        const size_t k0b = (size_t)(s & 15) * 64;
        const char* srcs[4];
        srcs[0] = (const char*)(pass ? A2p0 : A1p0) + (size_t)row0 * (DD * 2) + k0b;
        srcs[1] = (const char*)(pass ? A2p1 : A1p1) + (size_t)row0 * (DD * 2) + k0b;
        srcs[2] = (const char*)(pass ? W2p0 : W1p0) + (size_t)col0 * (DD * 2) + k0b;
        srcs[3] = (const char*)(pass ? W2p1 : W1p1) + (size_t)col0 * (DD * 2) + k0b;
        const uint32_t base = sb + slot * STAGE_BYTES;
        #pragma unroll
        for (int tile = 0; tile < 4; tile++) {
            #pragma unroll
            for (int hh = 0; hh < 2; hh++) {
                int j = hh * 256 + tid;
                int r = j >> 2, u = j & 3;
                cpasync16(base + tile * 8192 + SWZ(r * 64 + u * 16),
                          srcs[tile] + (size_t)r * (DD * 2) + u * 16);
            }
        }
        CP_COMMIT();
    };

    float acc[2][8][4];
    #pragma unroll
    for (int i = 0; i < 2; i++)
        #pragma unroll
        for (int j = 0; j < 8; j++)
            #pragma unroll
            for (int k = 0; k < 4; k++) acc[i][j][k] = 0.f;

    load_stage(0, 0);
    load_stage(1, 1);

    const int laA = lane & 15;
    const int luA = lane >> 4;
    const int laB = (lane & 7) + ((lane >> 4) << 3);
    const int luB = (lane >> 3) & 1;

    #pragma unroll 1
    for (int s = 0; s < KSTEPS; s++) {
        if (s + 2 < KSTEPS) load_stage(s + 2, (s + 2) % NSTAGE);
        else CP_COMMIT();
        CP_WAIT(2);
        __syncthreads();

        const uint32_t stg = sb + (s % NSTAGE) * STAGE_BYTES;
        #pragma unroll
        for (int kh = 0; kh < 2; kh++) {
            uint32_t A[2][2][4];   // [plane][am]
            #pragma unroll
            for (int am = 0; am < 2; am++) {
                uint32_t off = SWZ((warp_m + am * 16 + laA) * 64 + kh * 32 + luA * 16);
                ldsm4(A[0][am], stg + OFF_A0 + off);
                ldsm4(A[1][am], stg + OFF_A1 + off);
            }
            #pragma unroll
            for (int g = 0; g < 4; g++) {
                uint32_t Bf[2][4];
                uint32_t offb = SWZ((warp_n + g * 16 + laB) * 64 + kh * 32 + luB * 16);
                ldsm4(Bf[0], stg + OFF_B0 + offb);
                ldsm4(Bf[1], stg + OFF_B1 + offb);
                #pragma unroll
                for (int am = 0; am < 2; am++)
                    #pragma unroll
                    for (int sub = 0; sub < 2; sub++) {
                        float* c = acc[am][g * 2 + sub];
                        mma16816(c, A[0][am], &Bf[0][sub * 2]);
                        mma16816(c, A[0][am], &Bf[1][sub * 2]);
                        mma16816(c, A[1][am], &Bf[0][sub * 2]);
                    }
            }
        }
        __syncthreads();
    }

    // ---- fused LSTM cell epilogue ----
    const float* bias_s = (const float*)(smem + BIAS_OFF);
    const int q = lane & 3, r = lane >> 2;
    const int dbase = ((col0 + warp_n) >> 4) * 4 + q;
    #pragma unroll
    for (int am = 0; am < 2; am++) {
        #pragma unroll
        for (int half = 0; half < 2; half++) {
            const int m = row0 + warp_m + am * 16 + r + half * 8;
            const float* trow = nullptr;
            if (USE_TABLE) {
                int tv = tok[(size_t)m * tok_stride + tok_off];
                trow = tableOrBias + (size_t)tv * GG + col0 + warp_n + q * 2;
            }
            #pragma unroll
            for (int g16 = 0; g16 < 4; g16++) {
                float* aIF = acc[am][g16 * 2 + 0];
                float* aGO = acc[am][g16 * 2 + 1];
                float gi = aIF[half * 2 + 0], gf = aIF[half * 2 + 1];
                float gg = aGO[half * 2 + 0], go = aGO[half * 2 + 1];
                if (USE_TABLE) {
                    float2 t0 = *(const float2*)(trow + g16 * 16);
                    float2 t1 = *(const float2*)(trow + g16 * 16 + 8);
                    gi += t0.x; gf += t0.y; gg += t1.x; go += t1.y;
                } else {
                    int cb = warp_n + g16 * 16 + q * 2;
                    gi += bias_s[cb]; gf += bias_s[cb + 1];
                    gg += bias_s[cb + 8]; go += bias_s[cb + 9];
                }
                float I = sigf(gi), F = sigf(gf), G = tanhf(gg), O = sigf(go);
                int d = dbase + g16 * 4;
                size_t idx = (size_t)m * DD + d;
                float cn = F * c_state[idx] + I * G;
                float hn = O * tanhf(cn);
                c_state[idx] = cn;
                if (h_fp32) h_fp32[idx] = hn;
                fp16 a0, a1; split2(hn, a0, a1);
                h0o[idx] = a0; h1o[idx] = a1;
                if (x0o) { x0o[idx] = a0; x1o[idx] = a1; }
            }
        }
    }
}

// ---------------- prep kernels ----------------
// permute+split a [GG x DD] weight matrix into 2 fp16 planes with gate-interleaved rows
__global__ void permsplit_kernel(const float* __restrict__ W,
                                 fp16* __restrict__ p0, fp16* __restrict__ p1)
{
    size_t i = (size_t)blockIdx.x * 256 + threadIdx.x;
    if (i >= (size_t)GG * DD) return;
    int n = (int)(i >> 9), k = (int)(i & 511);
    int g = n >> 9, d = n & 511;
    int c = ((d >> 2) << 4) + ((d & 3) << 1) + ((g >> 1) << 3) + (g & 1);
    fp16 a0, a1;
    split2(W[i], a0, a1);
    size_t o = ((size_t)c << 9) + k;
    p0[o] = a0; p1[o] = a1;
}

__global__ void permbias_kernel(const float* __restrict__ b1, const float* __restrict__ b2,
                                float* __restrict__ bp)
{
    int n = blockIdx.x * 256 + threadIdx.x;
    if (n >= GG) return;
    int g = n >> 9, d = n & 511;
    int c = ((d >> 2) << 4) + ((d & 3) << 1) + ((g >> 1) << 3) + (g & 1);
    bp[c] = b1[n] + b2[n];
}

// exact fp32 table: table[v][c] = emb[v] . Wih_row(c) + bih + bhh, permuted cols
__global__ void table_kernel(const float* __restrict__ emb, const float* __restrict__ Wih,
                             const float* __restrict__ bih, const float* __restrict__ bhh,
                             float* __restrict__ table)
{
    __shared__ float es[DD];
    int v = blockIdx.x;
    int c = blockIdx.y * 128 + threadIdx.x;
    for (int i = threadIdx.x; i < DD; i += 128) es[i] = emb[(size_t)v * DD + i];
    __syncthreads();
    int d = ((c >> 4) << 2) + ((c >> 1) & 3);
    int g = (((c >> 3) & 1) << 1) + (c & 1);
    int n = g * 512 + d;
    const float* w = Wih + (size_t)n * DD;
    float acc = bih[n] + bhh[n];
    #pragma unroll 8
    for (int k = 0; k < DD; k++) acc = fmaf(es[k], w[k], acc);
    table[(size_t)v * GG + c] = acc;
}

// ---------------- fused logits + argmax ----------------
__global__ void logits_argmax_kernel(const float* __restrict__ h,
                                     const float* __restrict__ W,
                                     const float* __restrict__ bias,
                                     float* __restrict__ out, int t,
                                     int* __restrict__ pred)
{
    __shared__ float hs[DD];
    __shared__ float lg[DTGT];
    int b = blockIdx.x;
    for (int i = threadIdx.x; i < DD; i += blockDim.x)
        hs[i] = h[(size_t)b * DD + i];
    __syncthreads();
    int n = threadIdx.x;
    if (n < DTGT) {
        const float* w = W + (size_t)n * DD;
        float acc = bias[n];
        #pragma unroll 8
        for (int k = 0; k < DD; k++) acc = fmaf(hs[k], w[k], acc);
        lg[n] = acc;
        out[(size_t)b * (TTGT * DTGT) + t * DTGT + n] = acc;
    }
    __syncthreads();
    if (threadIdx.x == 0) {
        float best = lg[0];
        int bi = 0;
        for (int i = 1; i < DTGT; i++)
            if (lg[i] > best) { best = lg[i]; bi = i; }
        pred[b] = bi;
    }
}

// ---------------- host orchestration ----------------
extern "C" void kernel_launch(void* const* d_in, const int* in_sizes, int n_in,
                              void* d_out, int out_size)
{
    const int*   src     = (const int*)  d_in[0];
    const int*   tgt     = (const int*)  d_in[1];
    const float* enc_emb = (const float*)d_in[2];
    const float* dec_emb = (const float*)d_in[3];
    const float* enc_Wih = (const float*)d_in[4];
    const float* enc_Whh = (const float*)d_in[5];
    const float* enc_bih = (const float*)d_in[6];
    const float* enc_bhh = (const float*)d_in[7];
    const float* dec_Wih = (const float*)d_in[8];
    const float* dec_Whh = (const float*)d_in[9];
    const float* dec_bih = (const float*)d_in[10];
    const float* dec_bhh = (const float*)d_in[11];
    const float* post_W  = (const float*)d_in[12];
    const float* post_b  = (const float*)d_in[13];
    float* out = (float*)d_out;

    cudaFuncSetAttribute(gemm_cell<1, true>,  cudaFuncAttributeMaxDynamicSharedMemorySize, SMEM_TOTAL_GEMM);
    cudaFuncSetAttribute(gemm_cell<2, false>, cudaFuncAttributeMaxDynamicSharedMemorySize, SMEM_TOTAL_GEMM);

    fp16 *Xs0, *Xs1, *Wp0, *Wp1, *hp0, *hp1;
    float *cst, *hf, *encT, *decT, *biasE, *biasD;
    int* pred;
    cudaGetSymbolAddress((void**)&Xs0, g_Xs0);
    cudaGetSymbolAddress((void**)&Xs1, g_Xs1);
    cudaGetSymbolAddress((void**)&Wp0, g_Wp0);
    cudaGetSymbolAddress((void**)&Wp1, g_Wp1);
    cudaGetSymbolAddress((void**)&hp0, g_hp0);
    cudaGetSymbolAddress((void**)&hp1, g_hp1);
    cudaGetSymbolAddress((void**)&cst, g_c);
    cudaGetSymbolAddress((void**)&hf,  g_hf);
    cudaGetSymbolAddress((void**)&encT, g_encT);
    cudaGetSymbolAddress((void**)&decT, g_decT);
    cudaGetSymbolAddress((void**)&biasE, g_biasE);
    cudaGetSymbolAddress((void**)&biasD, g_biasD);
    cudaGetSymbolAddress((void**)&pred, g_pred);

    const size_t WSL = (size_t)GG * DD;
    const size_t HB  = (size_t)BB * DD;
    const size_t XT  = (size_t)BB * DD;

    // zero states
    cudaMemsetAsync(cst, 0, (size_t)NL * HB * sizeof(float), 0);
    cudaMemsetAsync(hp0, 0, (size_t)NL * 2 * HB * sizeof(fp16), 0);
    cudaMemsetAsync(hp1, 0, (size_t)NL * 2 * HB * sizeof(fp16), 0);

    // prep: permute+split weights [0]=encWhh0 [1]=encWih1 [2]=encWhh1 [3]=decWhh0 [4]=decWih1 [5]=decWhh1
    {
        int gsz = (int)((WSL + 255) / 256);
        permsplit_kernel<<<gsz, 256>>>(enc_Whh,        Wp0 + 0 * WSL, Wp1 + 0 * WSL);
        permsplit_kernel<<<gsz, 256>>>(enc_Wih + WSL,  Wp0 + 1 * WSL, Wp1 + 1 * WSL);
        permsplit_kernel<<<gsz, 256>>>(enc_Whh + WSL,  Wp0 + 2 * WSL, Wp1 + 2 * WSL);
        permsplit_kernel<<<gsz, 256>>>(dec_Whh,        Wp0 + 3 * WSL, Wp1 + 3 * WSL);
        permsplit_kernel<<<gsz, 256>>>(dec_Wih + WSL,  Wp0 + 4 * WSL, Wp1 + 4 * WSL);
        permsplit_kernel<<<gsz, 256>>>(dec_Whh + WSL,  Wp0 + 5 * WSL, Wp1 + 5 * WSL);
        permbias_kernel<<<(GG + 255) / 256, 256>>>(enc_bih + GG, enc_bhh + GG, biasE);
        permbias_kernel<<<(GG + 255) / 256, 256>>>(dec_bih + GG, dec_bhh + GG, biasD);
        table_kernel<<<dim3(DSRC, GG / 128), 128>>>(enc_emb, enc_Wih, enc_bih, enc_bhh, encT);
        table_kernel<<<dim3(DTGT, GG / 128), 128>>>(dec_emb, dec_Wih, dec_bih, dec_bhh, decT);
    }

    const dim3 gg(GG / CTA_N, BB / CTA_M);   // 16 x 16
    int p0 = 0, p1 = 0;                      // current-state parity per layer

    // ---- encoder layer 0 (h-GEMM + table gather, writes Xseq) ----
    for (int t = 0; t < TSRC; t++) {
        fp16* in0 = hp0 + (0 * 2 + p0) * HB;  fp16* ou0 = hp0 + (0 * 2 + (p0 ^ 1)) * HB;
        fp16* in1 = hp1 + (0 * 2 + p0) * HB;  fp16* ou1 = hp1 + (0 * 2 + (p0 ^ 1)) * HB;
        gemm_cell<1, true><<<gg, 256, SMEM_TOTAL_GEMM>>>(
            in0, in1, Wp0 + 0 * WSL, Wp1 + 0 * WSL,
            nullptr, nullptr, nullptr, nullptr,
            encT, src, TSRC, t,
            cst + 0 * HB, nullptr, ou0, ou1,
            Xs0 + (size_t)t * XT, Xs1 + (size_t)t * XT);
        p0 ^= 1;
    }
    // ---- encoder layer 1 (dual GEMM: Xseq + h) ----
    for (int t = 0; t < TSRC; t++) {
        fp16* in0 = hp0 + (1 * 2 + p1) * HB;  fp16* ou0 = hp0 + (1 * 2 + (p1 ^ 1)) * HB;
        fp16* in1 = hp1 + (1 * 2 + p1) * HB;  fp16* ou1 = hp1 + (1 * 2 + (p1 ^ 1)) * HB;
        gemm_cell<2, false><<<gg, 256, SMEM_TOTAL_GEMM>>>(
            Xs0 + (size_t)t * XT, Xs1 + (size_t)t * XT,
            Wp0 + 1 * WSL, Wp1 + 1 * WSL,
            in0, in1, Wp0 + 2 * WSL, Wp1 + 2 * WSL,
            biasE, nullptr, 0, 0,
            cst + 1 * HB, nullptr, ou0, ou1, nullptr, nullptr);
        p1 ^= 1;
    }

    // ---- decoder ----
    for (int t = 0; t < TTGT; t++) {
        // layer 0: h-GEMM + table gather by token (tgt[:,0] at t=0, else pred)
        fp16* i00 = hp0 + (0 * 2 + p0) * HB;  fp16* o00 = hp0 + (0 * 2 + (p0 ^ 1)) * HB;
        fp16* i01 = hp1 + (0 * 2 + p0) * HB;  fp16* o01 = hp1 + (0 * 2 + (p0 ^ 1)) * HB;
        const int* tk = t ? pred : tgt;
        int ts = t ? 1 : TTGT;
        gemm_cell<1, true><<<gg, 256, SMEM_TOTAL_GEMM>>>(
            i00, i01, Wp0 + 3 * WSL, Wp1 + 3 * WSL,
            nullptr, nullptr, nullptr, nullptr,
            decT, tk, ts, 0,
            cst + 0 * HB, nullptr, o00, o01, nullptr, nullptr);
        p0 ^= 1;
        // layer 1: dual GEMM (x = layer0 h of this step), writes fp32 h for logits
        fp16* i10 = hp0 + (1 * 2 + p1) * HB;  fp16* o10 = hp0 + (1 * 2 + (p1 ^ 1)) * HB;
        fp16* i11 = hp1 + (1 * 2 + p1) * HB;  fp16* o11 = hp1 + (1 * 2 + (p1 ^ 1)) * HB;
        gemm_cell<2, false><<<gg, 256, SMEM_TOTAL_GEMM>>>(
            o00, o01, Wp0 + 4 * WSL, Wp1 + 4 * WSL,
            i10, i11, Wp0 + 5 * WSL, Wp1 + 5 * WSL,
            biasD, nullptr, 0, 0,
            cst + 1 * HB, hf, o10, o11, nullptr, nullptr);
        p1 ^= 1;
        logits_argmax_kernel<<<BB, 128>>>(hf, post_W, post_b, out, t, pred);
    }
}

// round 7
// speedup vs baseline: 4.2801x; 1.9452x over previous
#include <cuda_runtime.h>
#include <cuda_fp16.h>
#include <math.h>
#include <stdint.h>

// Problem constants
#define BB    2048
#define DD    512
#define GG    2048
#define TSRC  32
#define TTGT  32
#define DTGT  80
#define DSRC  100
#define NL    2

// GEMM tiling
#define CTA_M 128
#define CTA_N 128
#define NSTAGE 3

#define STAGE_BYTES 32768
#define OFF_A0 0
#define OFF_A1 8192
#define OFF_B0 16384
#define OFF_B1 24576
#define BIAS_OFF (NSTAGE * STAGE_BYTES)          // 98304
#define SMEM_TOTAL_GEMM (BIAS_OFF + CTA_N * 4)   // 98816

#define SWZ(x) ((uint32_t)(x) ^ ((((uint32_t)(x)) >> 3) & 0x70))

typedef __half fp16;

// ---------------- persistent scratch ----------------
__device__ __align__(256) fp16 g_Xs0[(size_t)TSRC * BB * DD];
__device__ __align__(256) fp16 g_Xs1[(size_t)TSRC * BB * DD];
// permuted+split weights: [0]=encWhh0 [1]=encWih1 [2]=encWhh1 [3]=decWhh0 [4]=decWih1 [5]=decWhh1
__device__ __align__(256) fp16 g_Wp0[6][(size_t)GG * DD];
__device__ __align__(256) fp16 g_Wp1[6][(size_t)GG * DD];
__device__ __align__(256) fp16 g_hp0[NL][2][(size_t)BB * DD];
__device__ __align__(256) fp16 g_hp1[NL][2][(size_t)BB * DD];
__device__ float g_c[NL][(size_t)BB * DD];
__device__ float g_hf[(size_t)BB * DD];
__device__ float g_encT[(size_t)DSRC * GG];
__device__ float g_decT[(size_t)DTGT * GG];
__device__ float g_biasE[GG];
__device__ float g_biasD[GG];
__device__ int   g_pred[BB];

// ---------------- arg struct for runtime-dispatch GEMM ----------------
struct GArgs {
    const fp16 *A10, *A11, *W10, *W11;   // pass-0 operands
    const fp16 *A20, *A21, *W20, *W21;   // pass-1 operands
    const float* tb;                      // table (use_table) or permuted bias
    const int* tok; int tok_stride, tok_off;
    float* cst; float* hf;
    fp16 *h0o, *h1o, *x0o, *x1o;
    int npass; int use_table;
};

// ---------------- PTX helpers ----------------
__device__ __forceinline__ uint32_t smem_u32(const void* p) {
    uint32_t a;
    asm("{ .reg .u64 t; cvta.to.shared.u64 t, %1; cvt.u32.u64 %0, t; }" : "=r"(a) : "l"(p));
    return a;
}
__device__ __forceinline__ void cpasync16(uint32_t dst, const void* src) {
    asm volatile("cp.async.cg.shared.global [%0], [%1], 16;" :: "r"(dst), "l"(src));
}
#define CP_COMMIT()  asm volatile("cp.async.commit_group;" ::: "memory")
#define CP_WAIT(n)   asm volatile("cp.async.wait_group %0;" :: "n"(n) : "memory")

__device__ __forceinline__ void ldsm4(uint32_t* d, uint32_t addr) {
    asm volatile("ldmatrix.sync.aligned.m8n8.x4.shared.b16 {%0,%1,%2,%3}, [%4];"
        : "=r"(d[0]), "=r"(d[1]), "=r"(d[2]), "=r"(d[3]) : "r"(addr));
}
__device__ __forceinline__ void mma16816(float* c, const uint32_t* a, const uint32_t* b) {
    asm volatile(
        "mma.sync.aligned.m16n8k16.row.col.f32.f16.f16.f32 "
        "{%0,%1,%2,%3},{%4,%5,%6,%7},{%8,%9},{%0,%1,%2,%3};"
        : "+f"(c[0]), "+f"(c[1]), "+f"(c[2]), "+f"(c[3])
        : "r"(a[0]), "r"(a[1]), "r"(a[2]), "r"(a[3]), "r"(b[0]), "r"(b[1]));
}

__device__ __forceinline__ void split2(float x, fp16& a0, fp16& a1) {
    a0 = __float2half_rn(x);
    a1 = __float2half_rn(x - __half2float(a0));
}
__device__ __forceinline__ float sigf(float x) { return 1.f / (1.f + expf(-x)); }

// ---- fused GEMM + LSTM cell, runtime npass/use_table, grid.z dispatch ----
__global__ __launch_bounds__(256, 2)
void gemm_cell_dyn(GArgs a0, GArgs a1)
{
    const GArgs& a = (blockIdx.z == 1) ? a1 : a0;
    extern __shared__ char smem[];
    const uint32_t sb = smem_u32(smem);
    const int tid  = threadIdx.x;
    const int wid  = tid >> 5;
    const int lane = tid & 31;
    const int row0 = blockIdx.y * CTA_M;
    const int col0 = blockIdx.x * CTA_N;
    const int warp_m = (wid & 3) * 32;
    const int warp_n = (wid >> 2) * 64;
    const int KSTEPS = a.npass * 16;

    if (!a.use_table && tid < CTA_N)
        ((float*)(smem + BIAS_OFF))[tid] = a.tb[col0 + tid];

    auto load_stage = [&](int s, int slot) {
        const int pass = s >> 4;
        const size_t k0b = (size_t)(s & 15) * 64;
        const char* srcs[4];
        srcs[0] = (const char*)(pass ? a.A20 : a.A10) + (size_t)row0 * (DD * 2) + k0b;
        srcs[1] = (const char*)(pass ? a.A21 : a.A11) + (size_t)row0 * (DD * 2) + k0b;
        srcs[2] = (const char*)(pass ? a.W20 : a.W10) + (size_t)col0 * (DD * 2) + k0b;
        srcs[3] = (const char*)(pass ? a.W21 : a.W11) + (size_t)col0 * (DD * 2) + k0b;
        const uint32_t base = sb + slot * STAGE_BYTES;
        #pragma unroll
        for (int tile = 0; tile < 4; tile++) {
            #pragma unroll
            for (int hh = 0; hh < 2; hh++) {
                int j = hh * 256 + tid;
                int r = j >> 2, u = j & 3;
                cpasync16(base + tile * 8192 + SWZ(r * 64 + u * 16),
                          srcs[tile] + (size_t)r * (DD * 2) + u * 16);
            }
        }
        CP_COMMIT();
    };

    float acc[2][8][4];
    #pragma unroll
    for (int i = 0; i < 2; i++)
        #pragma unroll
        for (int j = 0; j < 8; j++)
            #pragma unroll
            for (int k = 0; k < 4; k++) acc[i][j][k] = 0.f;

    const int laA = lane & 15;
    const int luA = lane >> 4;
    const int laB = (lane & 7) + ((lane >> 4) << 3);
    const int luB = (lane >> 3) & 1;

    if (KSTEPS > 0) {
        load_stage(0, 0);
        load_stage(1, 1);

        #pragma unroll 1
        for (int s = 0; s < KSTEPS; s++) {
            if (s + 2 < KSTEPS) load_stage(s + 2, (s + 2) % NSTAGE);
            else CP_COMMIT();
            CP_WAIT(2);
            __syncthreads();

            const uint32_t stg = sb + (s % NSTAGE) * STAGE_BYTES;
            #pragma unroll
            for (int kh = 0; kh < 2; kh++) {
                uint32_t A[2][2][4];
                #pragma unroll
                for (int am = 0; am < 2; am++) {
                    uint32_t off = SWZ((warp_m + am * 16 + laA) * 64 + kh * 32 + luA * 16);
                    ldsm4(A[0][am], stg + OFF_A0 + off);
                    ldsm4(A[1][am], stg + OFF_A1 + off);
                }
                #pragma unroll
                for (int g = 0; g < 4; g++) {
                    uint32_t Bf[2][4];
                    uint32_t offb = SWZ((warp_n + g * 16 + laB) * 64 + kh * 32 + luB * 16);
                    ldsm4(Bf[0], stg + OFF_B0 + offb);
                    ldsm4(Bf[1], stg + OFF_B1 + offb);
                    #pragma unroll
                    for (int am = 0; am < 2; am++)
                        #pragma unroll
                        for (int sub = 0; sub < 2; sub++) {
                            float* c = acc[am][g * 2 + sub];
                            mma16816(c, A[0][am], &Bf[0][sub * 2]);
                            mma16816(c, A[0][am], &Bf[1][sub * 2]);
                            mma16816(c, A[1][am], &Bf[0][sub * 2]);
                        }
                }
            }
            __syncthreads();
        }
    } else {
        __syncthreads();   // cover bias visibility for npass==0 paths
    }

    // ---- fused LSTM cell epilogue ----
    const float* bias_s = (const float*)(smem + BIAS_OFF);
    const int q = lane & 3, r = lane >> 2;
    const int dbase = ((col0 + warp_n) >> 4) * 4 + q;
    #pragma unroll
    for (int am = 0; am < 2; am++) {
        #pragma unroll
        for (int half = 0; half < 2; half++) {
            const int m = row0 + warp_m + am * 16 + r + half * 8;
            const float* trow = nullptr;
            if (a.use_table) {
                int tv = a.tok[(size_t)m * a.tok_stride + a.tok_off];
                trow = a.tb + (size_t)tv * GG + col0 + warp_n + q * 2;
            }
            #pragma unroll
            for (int g16 = 0; g16 < 4; g16++) {
                float* aIF = acc[am][g16 * 2 + 0];
                float* aGO = acc[am][g16 * 2 + 1];
                float gi = aIF[half * 2 + 0], gf = aIF[half * 2 + 1];
                float gg = aGO[half * 2 + 0], go = aGO[half * 2 + 1];
                if (a.use_table) {
                    float2 t0 = *(const float2*)(trow + g16 * 16);
                    float2 t1 = *(const float2*)(trow + g16 * 16 + 8);
                    gi += t0.x; gf += t0.y; gg += t1.x; go += t1.y;
                } else {
                    int cb = warp_n + g16 * 16 + q * 2;
                    gi += bias_s[cb]; gf += bias_s[cb + 1];
                    gg += bias_s[cb + 8]; go += bias_s[cb + 9];
                }
                float I = sigf(gi), F = sigf(gf), G = tanhf(gg), O = sigf(go);
                int d = dbase + g16 * 4;
                size_t idx = (size_t)m * DD + d;
                float cn = F * a.cst[idx] + I * G;
                float hn = O * tanhf(cn);
                a.cst[idx] = cn;
                if (a.hf) a.hf[idx] = hn;
                fp16 v0, v1; split2(hn, v0, v1);
                a.h0o[idx] = v0; a.h1o[idx] = v1;
                if (a.x0o) { a.x0o[idx] = v0; a.x1o[idx] = v1; }
            }
        }
    }
}

// ---------------- fused prep kernels (3 launches total) ----------------
__global__ void permsplit_all(const float* w0, const float* w1, const float* w2,
                              const float* w3, const float* w4, const float* w5,
                              fp16* __restrict__ P0, fp16* __restrict__ P1)
{
    const float* srcs[6] = { w0, w1, w2, w3, w4, w5 };
    int mtx = blockIdx.y;
    size_t base = (size_t)mtx * GG * DD;
    size_t i = (size_t)blockIdx.x * 256 + threadIdx.x;
    if (i >= (size_t)GG * DD) return;
    int n = (int)(i >> 9), k = (int)(i & 511);
    int g = n >> 9, d = n & 511;
    int c = ((d >> 2) << 4) + ((d & 3) << 1) + ((g >> 1) << 3) + (g & 1);
    fp16 a0, a1;
    split2(srcs[mtx][i], a0, a1);
    size_t o = base + ((size_t)c << 9) + k;
    P0[o] = a0; P1[o] = a1;
}

__global__ void permbias_all(const float* e1, const float* e2,
                             const float* d1, const float* d2,
                             float* __restrict__ bE, float* __restrict__ bD)
{
    int n = blockIdx.x * 256 + threadIdx.x;
    if (n >= GG) return;
    int g = n >> 9, d = n & 511;
    int c = ((d >> 2) << 4) + ((d & 3) << 1) + ((g >> 1) << 3) + (g & 1);
    bE[c] = e1[n] + e2[n];
    bD[c] = d1[n] + d2[n];
}

__global__ void table_all(const float* __restrict__ eemb, const float* __restrict__ eW,
                          const float* __restrict__ eb1, const float* __restrict__ eb2,
                          const float* __restrict__ demb, const float* __restrict__ dW,
                          const float* __restrict__ db1, const float* __restrict__ db2,
                          float* __restrict__ eT, float* __restrict__ dT)
{
    __shared__ float es[DD];
    int v = blockIdx.x;
    bool enc = v < DSRC;
    int vv = enc ? v : v - DSRC;
    const float* emb = enc ? eemb : demb;
    const float* W   = enc ? eW : dW;
    const float* b1  = enc ? eb1 : db1;
    const float* b2  = enc ? eb2 : db2;
    float* T         = enc ? eT : dT;
    int c = blockIdx.y * 128 + threadIdx.x;
    for (int i = threadIdx.x; i < DD; i += 128) es[i] = emb[(size_t)vv * DD + i];
    __syncthreads();
    int d = ((c >> 4) << 2) + ((c >> 1) & 3);
    int g = (((c >> 3) & 1) << 1) + (c & 1);
    int n = g * 512 + d;
    const float* w = W + (size_t)n * DD;
    float acc = b1[n] + b2[n];
    #pragma unroll 8
    for (int k = 0; k < DD; k++) acc = fmaf(es[k], w[k], acc);
    T[(size_t)vv * GG + c] = acc;
}

// ---------------- warp-reduced logits + argmax ----------------
__global__ void logits_argmax_kernel(const float* __restrict__ h,
                                     const float* __restrict__ W,
                                     const float* __restrict__ bias,
                                     float* __restrict__ out, int t,
                                     int* __restrict__ pred)
{
    __shared__ float hs[DD];
    __shared__ float lg[DTGT];
    int b = blockIdx.x;
    int tid = threadIdx.x, wid = tid >> 5, lane = tid & 31;
    for (int i = tid; i < DD; i += 256)
        hs[i] = h[(size_t)b * DD + i];
    __syncthreads();
    #pragma unroll
    for (int j = 0; j < 10; j++) {
        int n = wid * 10 + j;
        const float* w = W + (size_t)n * DD;
        float acc = 0.f;
        #pragma unroll
        for (int k = lane; k < DD; k += 32) acc = fmaf(hs[k], w[k], acc);
        #pragma unroll
        for (int o = 16; o; o >>= 1) acc += __shfl_xor_sync(0xFFFFFFFFu, acc, o);
        if (lane == 0) {
            float v = acc + bias[n];
            lg[n] = v;
            out[(size_t)b * (TTGT * DTGT) + t * DTGT + n] = v;
        }
    }
    __syncthreads();
    if (tid == 0) {
        float best = lg[0];
        int bi = 0;
        for (int i = 1; i < DTGT; i++)
            if (lg[i] > best) { best = lg[i]; bi = i; }
        pred[b] = bi;
    }
}

// ---------------- host orchestration ----------------
extern "C" void kernel_launch(void* const* d_in, const int* in_sizes, int n_in,
                              void* d_out, int out_size)
{
    const int*   src     = (const int*)  d_in[0];
    const int*   tgt     = (const int*)  d_in[1];
    const float* enc_emb = (const float*)d_in[2];
    const float* dec_emb = (const float*)d_in[3];
    const float* enc_Wih = (const float*)d_in[4];
    const float* enc_Whh = (const float*)d_in[5];
    const float* enc_bih = (const float*)d_in[6];
    const float* enc_bhh = (const float*)d_in[7];
    const float* dec_Wih = (const float*)d_in[8];
    const float* dec_Whh = (const float*)d_in[9];
    const float* dec_bih = (const float*)d_in[10];
    const float* dec_bhh = (const float*)d_in[11];
    const float* post_W  = (const float*)d_in[12];
    const float* post_b  = (const float*)d_in[13];
    float* out = (float*)d_out;

    cudaFuncSetAttribute(gemm_cell_dyn, cudaFuncAttributeMaxDynamicSharedMemorySize, SMEM_TOTAL_GEMM);

    fp16 *Xs0, *Xs1, *Wp0, *Wp1, *hp0, *hp1;
    float *cst, *hf, *encT, *decT, *biasE, *biasD;
    int* pred;
    cudaGetSymbolAddress((void**)&Xs0, g_Xs0);
    cudaGetSymbolAddress((void**)&Xs1, g_Xs1);
    cudaGetSymbolAddress((void**)&Wp0, g_Wp0);
    cudaGetSymbolAddress((void**)&Wp1, g_Wp1);
    cudaGetSymbolAddress((void**)&hp0, g_hp0);
    cudaGetSymbolAddress((void**)&hp1, g_hp1);
    cudaGetSymbolAddress((void**)&cst, g_c);
    cudaGetSymbolAddress((void**)&hf,  g_hf);
    cudaGetSymbolAddress((void**)&encT, g_encT);
    cudaGetSymbolAddress((void**)&decT, g_decT);
    cudaGetSymbolAddress((void**)&biasE, g_biasE);
    cudaGetSymbolAddress((void**)&biasD, g_biasD);
    cudaGetSymbolAddress((void**)&pred, g_pred);

    const size_t WSL = (size_t)GG * DD;
    const size_t HB  = (size_t)BB * DD;

    cudaMemsetAsync(cst, 0, (size_t)NL * HB * sizeof(float), 0);

    // prep (3 kernels)
    permsplit_all<<<dim3((unsigned)((WSL + 255) / 256), 6), 256>>>(
        enc_Whh, enc_Wih + WSL, enc_Whh + WSL, dec_Whh, dec_Wih + WSL, dec_Whh + WSL, Wp0, Wp1);
    permbias_all<<<(GG + 255) / 256, 256>>>(enc_bih + GG, enc_bhh + GG,
                                            dec_bih + GG, dec_bhh + GG, biasE, biasD);
    table_all<<<dim3(DSRC + DTGT, GG / 128), 128>>>(
        enc_emb, enc_Wih, enc_bih, enc_bhh, dec_emb, dec_Wih, dec_bih, dec_bhh, encT, decT);

    int p0 = 0, p1 = 0;

    auto mk_l0_enc = [&](int t) {
        GArgs a = {};
        a.A10 = hp0 + (0 * 2 + p0) * HB;  a.A11 = hp1 + (0 * 2 + p0) * HB;
        a.W10 = Wp0 + 0 * WSL;            a.W11 = Wp1 + 0 * WSL;
        a.tb = encT; a.tok = src; a.tok_stride = TSRC; a.tok_off = t;
        a.cst = cst + 0 * HB; a.hf = nullptr;
        a.h0o = hp0 + (0 * 2 + (p0 ^ 1)) * HB;  a.h1o = hp1 + (0 * 2 + (p0 ^ 1)) * HB;
        a.x0o = Xs0 + (size_t)t * HB;  a.x1o = Xs1 + (size_t)t * HB;
        a.npass = (t == 0) ? 0 : 1; a.use_table = 1;
        return a;
    };
    auto mk_l1_enc = [&](int t) {
        GArgs a = {};
        a.A10 = Xs0 + (size_t)t * HB;  a.A11 = Xs1 + (size_t)t * HB;
        a.W10 = Wp0 + 1 * WSL;         a.W11 = Wp1 + 1 * WSL;
        a.A20 = hp0 + (1 * 2 + p1) * HB;  a.A21 = hp1 + (1 * 2 + p1) * HB;
        a.W20 = Wp0 + 2 * WSL;            a.W21 = Wp1 + 2 * WSL;
        a.tb = biasE; a.tok = nullptr; a.tok_stride = 0; a.tok_off = 0;
        a.cst = cst + 1 * HB; a.hf = nullptr;
        a.h0o = hp0 + (1 * 2 + (p1 ^ 1)) * HB;  a.h1o = hp1 + (1 * 2 + (p1 ^ 1)) * HB;
        a.x0o = nullptr; a.x1o = nullptr;
        a.npass = (t == 0) ? 1 : 2; a.use_table = 0;
        return a;
    };

    // ---- encoder: diagonal waves tau = 0..TSRC ----
    for (int tau = 0; tau <= TSRC; tau++) {
        bool has0 = (tau < TSRC);
        bool has1 = (tau >= 1);
        if (has0 && has1) {
            GArgs a0 = mk_l0_enc(tau);
            GArgs a1 = mk_l1_enc(tau - 1);
            gemm_cell_dyn<<<dim3(GG / CTA_N, BB / CTA_M, 2), 256, SMEM_TOTAL_GEMM>>>(a0, a1);
            p0 ^= 1; p1 ^= 1;
        } else if (has0) {
            GArgs a0 = mk_l0_enc(tau);
            gemm_cell_dyn<<<dim3(GG / CTA_N, BB / CTA_M, 1), 256, SMEM_TOTAL_GEMM>>>(a0, a0);
            p0 ^= 1;
        } else {
            GArgs a1 = mk_l1_enc(tau - 1);
            gemm_cell_dyn<<<dim3(GG / CTA_N, BB / CTA_M, 1), 256, SMEM_TOTAL_GEMM>>>(a1, a1);
            p1 ^= 1;
        }
    }

    // ---- decoder ----
    for (int t = 0; t < TTGT; t++) {
        // layer 0: h-GEMM + table gather
        GArgs a = {};
        a.A10 = hp0 + (0 * 2 + p0) * HB;  a.A11 = hp1 + (0 * 2 + p0) * HB;
        a.W10 = Wp0 + 3 * WSL;            a.W11 = Wp1 + 3 * WSL;
        a.tb = decT;
        a.tok = t ? pred : tgt;  a.tok_stride = t ? 1 : TTGT;  a.tok_off = 0;
        a.cst = cst + 0 * HB; a.hf = nullptr;
        a.h0o = hp0 + (0 * 2 + (p0 ^ 1)) * HB;  a.h1o = hp1 + (0 * 2 + (p0 ^ 1)) * HB;
        a.x0o = nullptr; a.x1o = nullptr;
        a.npass = 1; a.use_table = 1;
        gemm_cell_dyn<<<dim3(GG / CTA_N, BB / CTA_M, 1), 256, SMEM_TOTAL_GEMM>>>(a, a);
        p0 ^= 1;

        // layer 1: dual GEMM (x = layer0 h just written)
        GArgs b = {};
        b.A10 = hp0 + (0 * 2 + p0) * HB;  b.A11 = hp1 + (0 * 2 + p0) * HB;   // l0 output (parity flipped)
        b.W10 = Wp0 + 4 * WSL;            b.W11 = Wp1 + 4 * WSL;
        b.A20 = hp0 + (1 * 2 + p1) * HB;  b.A21 = hp1 + (1 * 2 + p1) * HB;
        b.W20 = Wp0 + 5 * WSL;            b.W21 = Wp1 + 5 * WSL;
        b.tb = biasD; b.tok = nullptr; b.tok_stride = 0; b.tok_off = 0;
        b.cst = cst + 1 * HB; b.hf = hf;
        b.h0o = hp0 + (1 * 2 + (p1 ^ 1)) * HB;  b.h1o = hp1 + (1 * 2 + (p1 ^ 1)) * HB;
        b.x0o = nullptr; b.x1o = nullptr;
        b.npass = 2; b.use_table = 0;
        gemm_cell_dyn<<<dim3(GG / CTA_N, BB / CTA_M, 1), 256, SMEM_TOTAL_GEMM>>>(b, b);
        p1 ^= 1;

        logits_argmax_kernel<<<BB, 256>>>(hf, post_W, post_b, out, t, pred);
    }
}